// round 1
// baseline (speedup 1.0000x reference)
#include <cuda_runtime.h>
#include <cuda_bf16.h>
#include <math.h>

#define D_MODEL   1024
#define NUM_HEADS 16
#define DK        64
#define BATCH     2
#define SEQ       2048
#define M_TOTAL   (BATCH * SEQ)          // 4096
#define HEADS_TOT (BATCH * NUM_HEADS)    // 32

// ---------------- scratch (no cudaMalloc allowed) ----------------
// Q, K, V in [B,H,S,DK] layout; attention output same layout.
__device__ float g_QKV[3][(size_t)HEADS_TOT * SEQ * DK];   // 3 x 16 MB
__device__ float g_AO[(size_t)HEADS_TOT * SEQ * DK];       // 16 MB

// =================================================================
// GEMM: 128x128 block, BK=16, 256 threads, 8x8 per thread.
// C = X[M,K] @ W^T  where W is [N,K] row-major (torch Linear weight).
// =================================================================
#define BM 128
#define BN 128
#define BK 16

// QKV projection: X = in_features [M_TOTAL, D], W selected by blockIdx.z,
// output scattered into head layout g_QKV[z].
__global__ __launch_bounds__(256, 1)
void gemm_qkv_kernel(const float* __restrict__ X,
                     const float* __restrict__ Wq,
                     const float* __restrict__ Wk,
                     const float* __restrict__ Wv)
{
    const float* __restrict__ W =
        (blockIdx.z == 0) ? Wq : ((blockIdx.z == 1) ? Wk : Wv);
    float* __restrict__ Out = g_QKV[blockIdx.z];

    __shared__ float As[BK][BM];
    __shared__ float Bs[BK][BN];

    const int tid = threadIdx.x;
    const int tx  = tid & 15;        // -> n
    const int ty  = tid >> 4;        // -> m
    const int m0  = blockIdx.y * BM;
    const int n0  = blockIdx.x * BN;

    const int lr = tid >> 2;         // 0..63 row within tile
    const int lk = (tid & 3) << 2;   // 0,4,8,12

    float acc[8][8];
#pragma unroll
    for (int i = 0; i < 8; i++)
#pragma unroll
        for (int j = 0; j < 8; j++) acc[i][j] = 0.f;

    for (int k0 = 0; k0 < D_MODEL; k0 += BK) {
        float4 a0 = *(const float4*)&X[(size_t)(m0 + lr)      * D_MODEL + k0 + lk];
        float4 a1 = *(const float4*)&X[(size_t)(m0 + lr + 64) * D_MODEL + k0 + lk];
        float4 b0 = *(const float4*)&W[(size_t)(n0 + lr)      * D_MODEL + k0 + lk];
        float4 b1 = *(const float4*)&W[(size_t)(n0 + lr + 64) * D_MODEL + k0 + lk];
        __syncthreads();
        As[lk + 0][lr] = a0.x; As[lk + 1][lr] = a0.y;
        As[lk + 2][lr] = a0.z; As[lk + 3][lr] = a0.w;
        As[lk + 0][lr + 64] = a1.x; As[lk + 1][lr + 64] = a1.y;
        As[lk + 2][lr + 64] = a1.z; As[lk + 3][lr + 64] = a1.w;
        Bs[lk + 0][lr] = b0.x; Bs[lk + 1][lr] = b0.y;
        Bs[lk + 2][lr] = b0.z; Bs[lk + 3][lr] = b0.w;
        Bs[lk + 0][lr + 64] = b1.x; Bs[lk + 1][lr + 64] = b1.y;
        Bs[lk + 2][lr + 64] = b1.z; Bs[lk + 3][lr + 64] = b1.w;
        __syncthreads();
#pragma unroll
        for (int k = 0; k < BK; k++) {
            float a[8], b[8];
            *(float4*)&a[0] = *(const float4*)&As[k][ty * 8];
            *(float4*)&a[4] = *(const float4*)&As[k][ty * 8 + 4];
            *(float4*)&b[0] = *(const float4*)&Bs[k][tx * 8];
            *(float4*)&b[4] = *(const float4*)&Bs[k][tx * 8 + 4];
#pragma unroll
            for (int i = 0; i < 8; i++)
#pragma unroll
                for (int j = 0; j < 8; j++)
                    acc[i][j] = fmaf(a[i], b[j], acc[i][j]);
        }
    }

    // scatter: feature n -> head h = n/64, t = n%64 ; row m -> (b,s)
    const int n  = n0 + tx * 8;
    const int h  = n >> 6;
    const int t  = n & 63;
#pragma unroll
    for (int i = 0; i < 8; i++) {
        const int mg = m0 + ty * 8 + i;
        const int b  = mg >> 11;           // / 2048
        const int s  = mg & (SEQ - 1);
        float* dst = &Out[(((size_t)b * NUM_HEADS + h) * SEQ + s) * DK + t];
        *(float4*)(dst)     = make_float4(acc[i][0], acc[i][1], acc[i][2], acc[i][3]);
        *(float4*)(dst + 4) = make_float4(acc[i][4], acc[i][5], acc[i][6], acc[i][7]);
    }
}

// Output projection: A gathered from head layout g_AO, C = d_out [M_TOTAL, D].
__global__ __launch_bounds__(256, 1)
void gemm_out_kernel(const float* __restrict__ Wo, float* __restrict__ C)
{
    __shared__ float As[BK][BM];
    __shared__ float Bs[BK][BN];

    const int tid = threadIdx.x;
    const int tx  = tid & 15;
    const int ty  = tid >> 4;
    const int m0  = blockIdx.y * BM;
    const int n0  = blockIdx.x * BN;

    const int lr = tid >> 2;
    const int lk = (tid & 3) << 2;

    float acc[8][8];
#pragma unroll
    for (int i = 0; i < 8; i++)
#pragma unroll
        for (int j = 0; j < 8; j++) acc[i][j] = 0.f;

    for (int k0 = 0; k0 < D_MODEL; k0 += BK) {
        const int kk = k0 + lk;
        const int h  = kk >> 6;
        const int t  = kk & 63;
        const int m_a0 = m0 + lr;
        const int m_a1 = m0 + lr + 64;
        // A[m][k] = g_AO[((b*H + h)*S + s)*DK + t]
        float4 a0 = *(const float4*)&g_AO[(((size_t)(m_a0 >> 11) * NUM_HEADS + h) * SEQ + (m_a0 & (SEQ - 1))) * DK + t];
        float4 a1 = *(const float4*)&g_AO[(((size_t)(m_a1 >> 11) * NUM_HEADS + h) * SEQ + (m_a1 & (SEQ - 1))) * DK + t];
        float4 b0 = *(const float4*)&Wo[(size_t)(n0 + lr)      * D_MODEL + kk];
        float4 b1 = *(const float4*)&Wo[(size_t)(n0 + lr + 64) * D_MODEL + kk];
        __syncthreads();
        As[lk + 0][lr] = a0.x; As[lk + 1][lr] = a0.y;
        As[lk + 2][lr] = a0.z; As[lk + 3][lr] = a0.w;
        As[lk + 0][lr + 64] = a1.x; As[lk + 1][lr + 64] = a1.y;
        As[lk + 2][lr + 64] = a1.z; As[lk + 3][lr + 64] = a1.w;
        Bs[lk + 0][lr] = b0.x; Bs[lk + 1][lr] = b0.y;
        Bs[lk + 2][lr] = b0.z; Bs[lk + 3][lr] = b0.w;
        Bs[lk + 0][lr + 64] = b1.x; Bs[lk + 1][lr + 64] = b1.y;
        Bs[lk + 2][lr + 64] = b1.z; Bs[lk + 3][lr + 64] = b1.w;
        __syncthreads();
#pragma unroll
        for (int k = 0; k < BK; k++) {
            float a[8], b[8];
            *(float4*)&a[0] = *(const float4*)&As[k][ty * 8];
            *(float4*)&a[4] = *(const float4*)&As[k][ty * 8 + 4];
            *(float4*)&b[0] = *(const float4*)&Bs[k][tx * 8];
            *(float4*)&b[4] = *(const float4*)&Bs[k][tx * 8 + 4];
#pragma unroll
            for (int i = 0; i < 8; i++)
#pragma unroll
                for (int j = 0; j < 8; j++)
                    acc[i][j] = fmaf(a[i], b[j], acc[i][j]);
        }
    }

#pragma unroll
    for (int i = 0; i < 8; i++) {
        const int mg = m0 + ty * 8 + i;
        float* dst = &C[(size_t)mg * D_MODEL + n0 + tx * 8];
        *(float4*)(dst)     = make_float4(acc[i][0], acc[i][1], acc[i][2], acc[i][3]);
        *(float4*)(dst + 4) = make_float4(acc[i][4], acc[i][5], acc[i][6], acc[i][7]);
    }
}

// =================================================================
// Flash attention (fp32, causal). One block = one head x 128 query rows.
// Thread t owns query row q0+t. KT=64 key tile.
// smem: Qs[128][68] (padded, conflict-free LDS.128) + Ks[64][64] + Vs[64][64]
// =================================================================
#define QT 128
#define KT 64
#define QS_STRIDE 68
#define ATTN_SMEM_FLOATS (QT * QS_STRIDE + KT * DK + KT * DK)
#define ATTN_SMEM_BYTES  (ATTN_SMEM_FLOATS * 4)

__global__ __launch_bounds__(QT, 1)
void attn_kernel()
{
    extern __shared__ float smem[];
    float* Qs = smem;                       // [128][68]
    float* Ks = smem + QT * QS_STRIDE;      // [64][64]
    float* Vs = Ks + KT * DK;               // [64][64]

    const int tid  = threadIdx.x;
    const int head = blockIdx.y;            // b*H + h
    const int q0   = blockIdx.x * QT;
    const int q    = q0 + tid;

    const float* Qg = g_QKV[0] + (size_t)head * SEQ * DK;
    const float* Kg = g_QKV[1] + (size_t)head * SEQ * DK;
    const float* Vg = g_QKV[2] + (size_t)head * SEQ * DK;

    // cooperative, coalesced Q tile load into padded smem
    {
        const float4* src = (const float4*)(Qg + (size_t)q0 * DK);
#pragma unroll
        for (int i = 0; i < 16; i++) {
            const int e   = i * QT + tid;       // float4 index, 0..2047
            const int row = e >> 4;
            const int c   = (e & 15) << 2;
            *(float4*)&Qs[row * QS_STRIDE + c] = src[e];
        }
    }

    float mrun = -1e30f, lrun = 0.f;
    float o[DK];
#pragma unroll
    for (int d = 0; d < DK; d++) o[d] = 0.f;

    const int ktiles = (q0 >> 6) + 2;           // causal: keys up to q0+127
    for (int kt = 0; kt < ktiles; kt++) {
        const int k0 = kt * KT;
        __syncthreads();
        {
            const float4* ksrc = (const float4*)(Kg + (size_t)k0 * DK);
            const float4* vsrc = (const float4*)(Vg + (size_t)k0 * DK);
#pragma unroll
            for (int i = 0; i < 8; i++) {
                const int e = i * QT + tid;     // 0..1023
                ((float4*)Ks)[e] = ksrc[e];
                ((float4*)Vs)[e] = vsrc[e];
            }
        }
        __syncthreads();

        // ---- scores: s[j] = (Q_row . K_j) / 8, causal-masked ----
        float s[KT];
#pragma unroll
        for (int j = 0; j < KT; j++) s[j] = 0.f;
#pragma unroll
        for (int d = 0; d < DK; d += 4) {
            const float4 qv = *(const float4*)&Qs[tid * QS_STRIDE + d];
#pragma unroll
            for (int j = 0; j < KT; j++) {
                const float4 kv = *(const float4*)&Ks[j * DK + d];
                s[j] = fmaf(qv.x, kv.x, s[j]);
                s[j] = fmaf(qv.y, kv.y, s[j]);
                s[j] = fmaf(qv.z, kv.z, s[j]);
                s[j] = fmaf(qv.w, kv.w, s[j]);
            }
        }
        float mt = mrun;
#pragma unroll
        for (int j = 0; j < KT; j++) {
            float v = s[j] * 0.125f;
            v = (k0 + j > q) ? -1e30f : v;
            s[j] = v;
            mt = fmaxf(mt, v);
        }

        // ---- online softmax rescale ----
        const float corr = __expf(mrun - mt);
        mrun = mt;
        lrun *= corr;
#pragma unroll
        for (int d = 0; d < DK; d++) o[d] *= corr;

        // ---- P @ V ----
#pragma unroll
        for (int j = 0; j < KT; j++) {
            const float p = __expf(s[j] - mt);
            lrun += p;
#pragma unroll
            for (int d = 0; d < DK; d += 4) {
                const float4 vv = *(const float4*)&Vs[j * DK + d];
                o[d]     = fmaf(p, vv.x, o[d]);
                o[d + 1] = fmaf(p, vv.y, o[d + 1]);
                o[d + 2] = fmaf(p, vv.z, o[d + 2]);
                o[d + 3] = fmaf(p, vv.w, o[d + 3]);
            }
        }
    }

    const float inv = 1.f / lrun;
    float* dst = g_AO + ((size_t)head * SEQ + q) * DK;
#pragma unroll
    for (int d = 0; d < DK; d += 4) {
        *(float4*)&dst[d] = make_float4(o[d] * inv, o[d + 1] * inv,
                                        o[d + 2] * inv, o[d + 3] * inv);
    }
}

// =================================================================
extern "C" void kernel_launch(void* const* d_in, const int* in_sizes, int n_in,
                              void* d_out, int out_size)
{
    const float* X  = (const float*)d_in[0];
    const float* Wq = (const float*)d_in[1];
    const float* Wk = (const float*)d_in[2];
    const float* Wv = (const float*)d_in[3];
    const float* Wo = (const float*)d_in[4];
    float* out = (float*)d_out;

    // attn kernel needs 67.6 KB dynamic smem (> 48 KB default)
    cudaFuncSetAttribute(attn_kernel,
                         cudaFuncAttributeMaxDynamicSharedMemorySize,
                         ATTN_SMEM_BYTES);

    dim3 gProj(D_MODEL / BN, M_TOTAL / BM, 3);     // (8, 32, 3)
    gemm_qkv_kernel<<<gProj, 256>>>(X, Wq, Wk, Wv);

    dim3 gAttn(SEQ / QT, HEADS_TOT);               // (16, 32)
    attn_kernel<<<gAttn, QT, ATTN_SMEM_BYTES>>>();

    dim3 gOut(D_MODEL / BN, M_TOTAL / BM);         // (8, 32)
    gemm_out_kernel<<<gOut, 256>>>(Wo, out);
}

// round 2
// speedup vs baseline: 1.4507x; 1.4507x over previous
#include <cuda_runtime.h>
#include <cuda_bf16.h>
#include <math.h>

#define D_MODEL   1024
#define NUM_HEADS 16
#define DK        64
#define BATCH     2
#define SEQ       2048
#define M_TOTAL   (BATCH * SEQ)          // 4096
#define HEADS_TOT (BATCH * NUM_HEADS)    // 32

typedef unsigned long long u64;

// ---------------- scratch (no cudaMalloc allowed) ----------------
__device__ float g_QKV[3][(size_t)HEADS_TOT * SEQ * DK];   // 3 x 16 MB
__device__ float g_AO[(size_t)HEADS_TOT * SEQ * DK];       // 16 MB

// ---------------- packed fp32x2 helpers (sm_103a FFMA2) ----------------
__device__ __forceinline__ void fma2(u64& d, u64 a, u64 b) {
    asm("fma.rn.f32x2 %0, %1, %2, %0;" : "+l"(d) : "l"(a), "l"(b));
}
__device__ __forceinline__ u64 mul2(u64 a, u64 b) {
    u64 r; asm("mul.rn.f32x2 %0, %1, %2;" : "=l"(r) : "l"(a), "l"(b)); return r;
}
__device__ __forceinline__ u64 rep2(float x) {
    u64 r; asm("mov.b64 %0, {%1, %1};" : "=l"(r) : "f"(x)); return r;
}
__device__ __forceinline__ void unpk2(u64 v, float& lo, float& hi) {
    asm("mov.b64 {%0, %1}, %2;" : "=f"(lo), "=f"(hi) : "l"(v));
}

// =================================================================
// GEMM: 128x128 block, BK=16, 256 threads, 8x8 per thread (FFMA2).
// C = X[M,K] @ W^T  where W is [N,K] row-major.
// =================================================================
#define BM 128
#define BN 128
#define BK 16

__device__ __forceinline__ void gemm_tile_math(
    const float (*As)[BM], const float (*Bs)[BN],
    int ty, int tx, u64 acc[8][4])
{
#pragma unroll
    for (int k = 0; k < BK; k++) {
        float a[8];
        *(float4*)&a[0] = *(const float4*)&As[k][ty * 8];
        *(float4*)&a[4] = *(const float4*)&As[k][ty * 8 + 4];
        u64 b2[4];
        {
            ulonglong2 t0 = *(const ulonglong2*)&Bs[k][tx * 8];
            ulonglong2 t1 = *(const ulonglong2*)&Bs[k][tx * 8 + 4];
            b2[0] = t0.x; b2[1] = t0.y; b2[2] = t1.x; b2[3] = t1.y;
        }
#pragma unroll
        for (int i = 0; i < 8; i++) {
            u64 a2 = rep2(a[i]);
#pragma unroll
            for (int j = 0; j < 4; j++) fma2(acc[i][j], a2, b2[j]);
        }
    }
}

// QKV projection, output scattered into [B,H,S,DK] layout.
__global__ __launch_bounds__(256, 1)
void gemm_qkv_kernel(const float* __restrict__ X,
                     const float* __restrict__ Wq,
                     const float* __restrict__ Wk,
                     const float* __restrict__ Wv)
{
    const float* __restrict__ W =
        (blockIdx.z == 0) ? Wq : ((blockIdx.z == 1) ? Wk : Wv);
    float* __restrict__ Out = g_QKV[blockIdx.z];

    __shared__ float As[BK][BM];
    __shared__ float Bs[BK][BN];

    const int tid = threadIdx.x;
    const int tx  = tid & 15;
    const int ty  = tid >> 4;
    const int m0  = blockIdx.y * BM;
    const int n0  = blockIdx.x * BN;
    const int lr  = tid >> 2;
    const int lk  = (tid & 3) << 2;

    u64 acc[8][4];
#pragma unroll
    for (int i = 0; i < 8; i++)
#pragma unroll
        for (int j = 0; j < 4; j++) acc[i][j] = 0ull;

    for (int k0 = 0; k0 < D_MODEL; k0 += BK) {
        float4 a0 = *(const float4*)&X[(size_t)(m0 + lr)      * D_MODEL + k0 + lk];
        float4 a1 = *(const float4*)&X[(size_t)(m0 + lr + 64) * D_MODEL + k0 + lk];
        float4 b0 = *(const float4*)&W[(size_t)(n0 + lr)      * D_MODEL + k0 + lk];
        float4 b1 = *(const float4*)&W[(size_t)(n0 + lr + 64) * D_MODEL + k0 + lk];
        __syncthreads();
        As[lk + 0][lr] = a0.x; As[lk + 1][lr] = a0.y;
        As[lk + 2][lr] = a0.z; As[lk + 3][lr] = a0.w;
        As[lk + 0][lr + 64] = a1.x; As[lk + 1][lr + 64] = a1.y;
        As[lk + 2][lr + 64] = a1.z; As[lk + 3][lr + 64] = a1.w;
        Bs[lk + 0][lr] = b0.x; Bs[lk + 1][lr] = b0.y;
        Bs[lk + 2][lr] = b0.z; Bs[lk + 3][lr] = b0.w;
        Bs[lk + 0][lr + 64] = b1.x; Bs[lk + 1][lr + 64] = b1.y;
        Bs[lk + 2][lr + 64] = b1.z; Bs[lk + 3][lr + 64] = b1.w;
        __syncthreads();
        gemm_tile_math(As, Bs, ty, tx, acc);
    }

    const int n = n0 + tx * 8;
    const int h = n >> 6;
    const int t = n & 63;
#pragma unroll
    for (int i = 0; i < 8; i++) {
        const int mg = m0 + ty * 8 + i;
        const int b  = mg >> 11;
        const int s  = mg & (SEQ - 1);
        float* dst = &Out[(((size_t)b * NUM_HEADS + h) * SEQ + s) * DK + t];
        *(ulonglong2*)(dst)     = make_ulonglong2(acc[i][0], acc[i][1]);
        *(ulonglong2*)(dst + 4) = make_ulonglong2(acc[i][2], acc[i][3]);
    }
}

// Output projection: A gathered from head layout g_AO, C = d_out.
__global__ __launch_bounds__(256, 1)
void gemm_out_kernel(const float* __restrict__ Wo, float* __restrict__ C)
{
    __shared__ float As[BK][BM];
    __shared__ float Bs[BK][BN];

    const int tid = threadIdx.x;
    const int tx  = tid & 15;
    const int ty  = tid >> 4;
    const int m0  = blockIdx.y * BM;
    const int n0  = blockIdx.x * BN;
    const int lr  = tid >> 2;
    const int lk  = (tid & 3) << 2;

    u64 acc[8][4];
#pragma unroll
    for (int i = 0; i < 8; i++)
#pragma unroll
        for (int j = 0; j < 4; j++) acc[i][j] = 0ull;

    for (int k0 = 0; k0 < D_MODEL; k0 += BK) {
        const int kk = k0 + lk;
        const int h  = kk >> 6;
        const int t  = kk & 63;
        const int m_a0 = m0 + lr;
        const int m_a1 = m0 + lr + 64;
        float4 a0 = *(const float4*)&g_AO[(((size_t)(m_a0 >> 11) * NUM_HEADS + h) * SEQ + (m_a0 & (SEQ - 1))) * DK + t];
        float4 a1 = *(const float4*)&g_AO[(((size_t)(m_a1 >> 11) * NUM_HEADS + h) * SEQ + (m_a1 & (SEQ - 1))) * DK + t];
        float4 b0 = *(const float4*)&Wo[(size_t)(n0 + lr)      * D_MODEL + kk];
        float4 b1 = *(const float4*)&Wo[(size_t)(n0 + lr + 64) * D_MODEL + kk];
        __syncthreads();
        As[lk + 0][lr] = a0.x; As[lk + 1][lr] = a0.y;
        As[lk + 2][lr] = a0.z; As[lk + 3][lr] = a0.w;
        As[lk + 0][lr + 64] = a1.x; As[lk + 1][lr + 64] = a1.y;
        As[lk + 2][lr + 64] = a1.z; As[lk + 3][lr + 64] = a1.w;
        Bs[lk + 0][lr] = b0.x; Bs[lk + 1][lr] = b0.y;
        Bs[lk + 2][lr] = b0.z; Bs[lk + 3][lr] = b0.w;
        Bs[lk + 0][lr + 64] = b1.x; Bs[lk + 1][lr + 64] = b1.y;
        Bs[lk + 2][lr + 64] = b1.z; Bs[lk + 3][lr + 64] = b1.w;
        __syncthreads();
        gemm_tile_math(As, Bs, ty, tx, acc);
    }

#pragma unroll
    for (int i = 0; i < 8; i++) {
        const int mg = m0 + ty * 8 + i;
        float* dst = &C[(size_t)mg * D_MODEL + n0 + tx * 8];
        *(ulonglong2*)(dst)     = make_ulonglong2(acc[i][0], acc[i][1]);
        *(ulonglong2*)(dst + 4) = make_ulonglong2(acc[i][2], acc[i][3]);
    }
}

// =================================================================
// Flash attention (fp32 FFMA2, causal). Block = one head x 128 q rows.
// K stored d-major (transposed) so key pairs pack; V row-major so d pairs pack.
// =================================================================
#define QT 128
#define KT 64
#define QSTR 65                         // conflict-free scalar q loads
#define KSTR 68                         // 16B-aligned j-pair loads
#define ATTN_SMEM_FLOATS (QT * QSTR + DK * KSTR + KT * DK)
#define ATTN_SMEM_BYTES  (ATTN_SMEM_FLOATS * 4)

__global__ __launch_bounds__(QT, 3)
void attn_kernel()
{
    extern __shared__ float smem[];
    float* Qs  = smem;                       // [128][65]
    float* Kst = smem + QT * QSTR;           // [64][68]  (d-major)
    float* Vs  = Kst + DK * KSTR;            // [64][64]  (j-major)

    const int tid  = threadIdx.x;
    const int head = blockIdx.y;
    const int q0   = (gridDim.x - 1 - blockIdx.x) * QT;   // heavy blocks first
    const int q    = q0 + tid;

    const float* Qg = g_QKV[0] + (size_t)head * SEQ * DK;
    const float* Kg = g_QKV[1] + (size_t)head * SEQ * DK;
    const float* Vg = g_QKV[2] + (size_t)head * SEQ * DK;

    // coalesced Q tile load -> padded smem (stride 65)
    {
        const float4* src = (const float4*)(Qg + (size_t)q0 * DK);
#pragma unroll
        for (int i = 0; i < 16; i++) {
            const int e   = i * QT + tid;
            const int row = e >> 4;
            const int c   = (e & 15) << 2;
            float4 v = src[e];
            float* p = &Qs[row * QSTR + c];
            p[0] = v.x; p[1] = v.y; p[2] = v.z; p[3] = v.w;
        }
    }

    float mrun = -1e30f, lrun = 0.f;
    u64 o2[32];
#pragma unroll
    for (int d = 0; d < 32; d++) o2[d] = 0ull;

    const int ktiles = (q0 >> 6) + 2;
    for (int kt = 0; kt < ktiles; kt++) {
        const int k0 = kt * KT;
        __syncthreads();
        {
            const float4* ksrc = (const float4*)(Kg + (size_t)k0 * DK);
            const float4* vsrc = (const float4*)(Vg + (size_t)k0 * DK);
#pragma unroll
            for (int i = 0; i < 8; i++) {
                const int e  = i * QT + tid;     // 0..1023
                const int j  = e >> 4;
                const int d0 = (e & 15) << 2;
                float4 kv = ksrc[e];
                Kst[(d0 + 0) * KSTR + j] = kv.x;
                Kst[(d0 + 1) * KSTR + j] = kv.y;
                Kst[(d0 + 2) * KSTR + j] = kv.z;
                Kst[(d0 + 3) * KSTR + j] = kv.w;
                ((float4*)Vs)[e] = vsrc[e];
            }
        }
        __syncthreads();

        // ---- scores (packed over key pairs) ----
        u64 s2[32];
#pragma unroll
        for (int j = 0; j < 32; j++) s2[j] = 0ull;
#pragma unroll 4
        for (int d = 0; d < DK; d++) {
            const u64 q2 = rep2(Qs[tid * QSTR + d]);
            const ulonglong2* krow = (const ulonglong2*)&Kst[d * KSTR];
#pragma unroll
            for (int j4 = 0; j4 < 16; j4++) {
                ulonglong2 kk = krow[j4];
                fma2(s2[2 * j4],     q2, kk.x);
                fma2(s2[2 * j4 + 1], q2, kk.y);
            }
        }

        // ---- scale + causal mask + running max ----
        float s[KT];
        float mt = mrun;
#pragma unroll
        for (int j2 = 0; j2 < 32; j2++) {
            float lo, hi;
            unpk2(s2[j2], lo, hi);
            lo *= 0.125f; hi *= 0.125f;
            const int jl = 2 * j2, jh = 2 * j2 + 1;
            lo = (k0 + jl > q) ? -1e30f : lo;
            hi = (k0 + jh > q) ? -1e30f : hi;
            s[jl] = lo; s[jh] = hi;
            mt = fmaxf(mt, fmaxf(lo, hi));
        }

        // ---- rescale ----
        const float corr = __expf(mrun - mt);
        mrun = mt;
        lrun *= corr;
        const u64 c2 = rep2(corr);
#pragma unroll
        for (int d = 0; d < 32; d++) o2[d] = mul2(o2[d], c2);

        // ---- P @ V (packed over d pairs) ----
#pragma unroll 2
        for (int j = 0; j < KT; j++) {
            const float p = __expf(s[j] - mt);
            lrun += p;
            const u64 p2 = rep2(p);
            const ulonglong2* vrow = (const ulonglong2*)&Vs[j * DK];
#pragma unroll
            for (int d4 = 0; d4 < 16; d4++) {
                ulonglong2 vv = vrow[d4];
                fma2(o2[2 * d4],     p2, vv.x);
                fma2(o2[2 * d4 + 1], p2, vv.y);
            }
        }
    }

    const u64 inv2 = rep2(1.f / lrun);
    float* dst = g_AO + ((size_t)head * SEQ + q) * DK;
#pragma unroll
    for (int d2 = 0; d2 < 16; d2++) {
        u64 a = mul2(o2[2 * d2], inv2);
        u64 b = mul2(o2[2 * d2 + 1], inv2);
        *(ulonglong2*)&dst[d2 * 4] = make_ulonglong2(a, b);
    }
}

// =================================================================
extern "C" void kernel_launch(void* const* d_in, const int* in_sizes, int n_in,
                              void* d_out, int out_size)
{
    const float* X  = (const float*)d_in[0];
    const float* Wq = (const float*)d_in[1];
    const float* Wk = (const float*)d_in[2];
    const float* Wv = (const float*)d_in[3];
    const float* Wo = (const float*)d_in[4];
    float* out = (float*)d_out;

    cudaFuncSetAttribute(attn_kernel,
                         cudaFuncAttributeMaxDynamicSharedMemorySize,
                         ATTN_SMEM_BYTES);

    dim3 gProj(D_MODEL / BN, M_TOTAL / BM, 3);     // (8, 32, 3)
    gemm_qkv_kernel<<<gProj, 256>>>(X, Wq, Wk, Wv);

    dim3 gAttn(SEQ / QT, HEADS_TOT);               // (16, 32)
    attn_kernel<<<gAttn, QT, ATTN_SMEM_BYTES>>>();

    dim3 gOut(D_MODEL / BN, M_TOTAL / BM);         // (8, 32)
    gemm_out_kernel<<<gOut, 256>>>(Wo, out);
}

// round 4
// speedup vs baseline: 2.0520x; 1.4145x over previous
#include <cuda_runtime.h>
#include <cuda_bf16.h>
#include <cstdint>
#include <math.h>

#define D_MODEL   1024
#define NUM_HEADS 16
#define DK        64
#define BATCH     2
#define SEQ       2048
#define M_TOTAL   (BATCH * SEQ)          // 4096
#define HEADS_TOT (BATCH * NUM_HEADS)    // 32

typedef unsigned long long u64;

// ---------------- scratch (no cudaMalloc allowed) ----------------
__device__ float g_QKV[3][(size_t)HEADS_TOT * SEQ * DK];   // 48 MB fp32
// split-bf16 operands
__device__ __nv_bfloat16 g_Xh[(size_t)M_TOTAL * D_MODEL];
__device__ __nv_bfloat16 g_Xl[(size_t)M_TOTAL * D_MODEL];
__device__ __nv_bfloat16 g_Wh[4][(size_t)D_MODEL * D_MODEL];
__device__ __nv_bfloat16 g_Wl[4][(size_t)D_MODEL * D_MODEL];
__device__ __nv_bfloat16 g_Ah[(size_t)HEADS_TOT * SEQ * DK];  // attn out hi
__device__ __nv_bfloat16 g_Al[(size_t)HEADS_TOT * SEQ * DK];  // attn out lo

// ---------------- ptx helpers ----------------
__device__ __forceinline__ uint32_t smem_u32(const void* p) {
    uint32_t a;
    asm("{ .reg .u64 t; cvta.to.shared.u64 t, %1; cvt.u32.u64 %0, t; }" : "=r"(a) : "l"(p));
    return a;
}
__device__ __forceinline__ void cp16(uint32_t dst, const void* src) {
    asm volatile("cp.async.cg.shared.global [%0], [%1], 16;" :: "r"(dst), "l"(src));
}
#define CP_COMMIT() asm volatile("cp.async.commit_group;" ::: "memory")
#define CP_WAIT(n)  asm volatile("cp.async.wait_group %0;" :: "n"(n) : "memory")

__device__ __forceinline__ void ldsm4(uint32_t& r0, uint32_t& r1, uint32_t& r2, uint32_t& r3,
                                      uint32_t addr) {
    asm volatile("ldmatrix.sync.aligned.m8n8.x4.shared.b16 {%0,%1,%2,%3}, [%4];"
                 : "=r"(r0), "=r"(r1), "=r"(r2), "=r"(r3) : "r"(addr));
}
__device__ __forceinline__ void mma16816(float* d, const uint32_t* a, const uint32_t* b) {
    asm volatile("mma.sync.aligned.m16n8k16.row.col.f32.bf16.bf16.f32 "
        "{%0,%1,%2,%3}, {%4,%5,%6,%7}, {%8,%9}, {%0,%1,%2,%3};"
        : "+f"(d[0]), "+f"(d[1]), "+f"(d[2]), "+f"(d[3])
        : "r"(a[0]), "r"(a[1]), "r"(a[2]), "r"(a[3]), "r"(b[0]), "r"(b[1]));
}

// ---------------- packed fp32x2 helpers (attention) ----------------
__device__ __forceinline__ void fma2(u64& d, u64 a, u64 b) {
    asm("fma.rn.f32x2 %0, %1, %2, %0;" : "+l"(d) : "l"(a), "l"(b));
}
__device__ __forceinline__ u64 mul2(u64 a, u64 b) {
    u64 r; asm("mul.rn.f32x2 %0, %1, %2;" : "=l"(r) : "l"(a), "l"(b)); return r;
}
__device__ __forceinline__ u64 rep2(float x) {
    u64 r; asm("mov.b64 %0, {%1, %1};" : "=l"(r) : "f"(x)); return r;
}
__device__ __forceinline__ void unpk2(u64 v, float& lo, float& hi) {
    asm("mov.b64 {%0, %1}, %2;" : "=f"(lo), "=f"(hi) : "l"(v));
}

// =================================================================
// fp32 -> (hi, lo) bf16 split, elementwise
// =================================================================
__global__ __launch_bounds__(256)
void cvt_kernel(const float* __restrict__ src,
                __nv_bfloat16* __restrict__ hi,
                __nv_bfloat16* __restrict__ lo, int n4)
{
    int i = blockIdx.x * 256 + threadIdx.x;
    if (i >= n4) return;
    float4 v = ((const float4*)src)[i];
    __nv_bfloat16 h0 = __float2bfloat16(v.x), h1 = __float2bfloat16(v.y);
    __nv_bfloat16 h2 = __float2bfloat16(v.z), h3 = __float2bfloat16(v.w);
    __nv_bfloat16 l0 = __float2bfloat16(v.x - __bfloat162float(h0));
    __nv_bfloat16 l1 = __float2bfloat16(v.y - __bfloat162float(h1));
    __nv_bfloat16 l2 = __float2bfloat16(v.z - __bfloat162float(h2));
    __nv_bfloat16 l3 = __float2bfloat16(v.w - __bfloat162float(h3));
    ((__nv_bfloat162*)hi)[2 * i]     = __nv_bfloat162(h0, h1);
    ((__nv_bfloat162*)hi)[2 * i + 1] = __nv_bfloat162(h2, h3);
    ((__nv_bfloat162*)lo)[2 * i]     = __nv_bfloat162(l0, l1);
    ((__nv_bfloat162*)lo)[2 * i + 1] = __nv_bfloat162(l2, l3);
}

// =================================================================
// split-bf16 HMMA GEMM: block 128x128, BK=32, 8 warps (4x2), warp 32x64.
// C = A[M,1024] @ W^T, 3 MMAs (hh,hl,lh) per pair -> fp32-class accuracy.
// =================================================================
#define BM 128
#define BN 128
#define BK 32
#define SSTR   40                        // bf16 row stride (80 B) — LDSM conflict-free
#define TILE_B (BM * SSTR * 2)           // 10240 B per tile
#define STAGE_B (4 * TILE_B)             // Ah, Al, Bh, Bl
#define GEMM_SMEM (2 * STAGE_B)          // 81920 B double-buffered

// stage copy: 4 tiles x 128 rows x 32 bf16; 8 cp.async(16B) per thread
template<bool QKV>
__device__ __forceinline__ void issue_copies(uint32_t stage_sb, int tid, int m0, int n0, int kc,
                                             const __nv_bfloat16* __restrict__ Wh,
                                             const __nv_bfloat16* __restrict__ Wl)
{
    const int k0 = kc * BK;
#pragma unroll
    for (int o = 0; o < 8; o++) {
        const int e    = o * 256 + tid;
        const int tile = e >> 9;            // 0 Ah, 1 Al, 2 Bh, 3 Bl
        const int idx  = e & 511;
        const int r = idx >> 2, c = idx & 3;
        const uint32_t dst = stage_sb + tile * TILE_B + r * (SSTR * 2) + c * 16;
        const __nv_bfloat16* src;
        if (tile < 2) {
            size_t ai;
            if (QKV) {
                ai = (size_t)(m0 + r) * D_MODEL + k0 + c * 8;
            } else {
                const int m = m0 + r;
                ai = (((size_t)(m >> 11) * NUM_HEADS + (k0 >> 6)) * SEQ + (m & (SEQ - 1))) * DK
                     + (k0 & 63) + c * 8;
            }
            src = (tile == 0 ? (QKV ? g_Xh : g_Ah) : (QKV ? g_Xl : g_Al)) + ai;
        } else {
            const size_t bi = (size_t)(n0 + r) * D_MODEL + k0 + c * 8;
            src = (tile == 2 ? Wh : Wl) + bi;
        }
        cp16(dst, src);
    }
}

__device__ __forceinline__ void mma_stage(uint32_t Abase, int lane, int wm, int wn,
                                          float acc[2][8][4])
{
#pragma unroll
    for (int h = 0; h < 2; h++) {                   // two k16 halves of BK=32
        uint32_t ah[2][4], al[2][4];
#pragma unroll
        for (int mt = 0; mt < 2; mt++) {
            const uint32_t addr = Abase
                + (uint32_t)(wm * 32 + mt * 16 + (lane & 15)) * (SSTR * 2)
                + h * 32 + ((lane >> 4) << 4);
            ldsm4(ah[mt][0], ah[mt][1], ah[mt][2], ah[mt][3], addr);
            ldsm4(al[mt][0], al[mt][1], al[mt][2], al[mt][3], addr + TILE_B);
        }
        uint32_t bh[4][4], bl[4][4];
#pragma unroll
        for (int nt = 0; nt < 4; nt++) {
            const uint32_t addr = Abase + 2 * TILE_B
                + (uint32_t)(wn * 64 + nt * 16 + (lane & 7) + ((lane >> 4) << 3)) * (SSTR * 2)
                + h * 32 + (((lane >> 3) & 1) << 4);
            ldsm4(bh[nt][0], bh[nt][1], bh[nt][2], bh[nt][3], addr);
            ldsm4(bl[nt][0], bl[nt][1], bl[nt][2], bl[nt][3], addr + TILE_B);
        }
#pragma unroll
        for (int mt = 0; mt < 2; mt++)
#pragma unroll
            for (int nt = 0; nt < 4; nt++) {
                mma16816(acc[mt][2 * nt],     ah[mt], &bh[nt][0]);
                mma16816(acc[mt][2 * nt + 1], ah[mt], &bh[nt][2]);
                mma16816(acc[mt][2 * nt],     ah[mt], &bl[nt][0]);
                mma16816(acc[mt][2 * nt + 1], ah[mt], &bl[nt][2]);
                mma16816(acc[mt][2 * nt],     al[mt], &bh[nt][0]);
                mma16816(acc[mt][2 * nt + 1], al[mt], &bh[nt][2]);
            }
    }
}

template<bool QKV>
__device__ __forceinline__ void gemm_body(float acc[2][8][4], uint32_t sb, int tid,
                                          int m0, int n0,
                                          const __nv_bfloat16* __restrict__ Wh,
                                          const __nv_bfloat16* __restrict__ Wl)
{
    const int lane = tid & 31, wid = tid >> 5;
    const int wm = wid >> 1, wn = wid & 1;
    const int NKC = D_MODEL / BK;                   // 32

    issue_copies<QKV>(sb, tid, m0, n0, 0, Wh, Wl);
    CP_COMMIT();
    for (int kc = 0; kc < NKC; kc++) {
        if (kc + 1 < NKC) {
            issue_copies<QKV>(sb + ((kc + 1) & 1) * STAGE_B, tid, m0, n0, kc + 1, Wh, Wl);
            CP_COMMIT();
            CP_WAIT(1);
        } else {
            CP_WAIT(0);
        }
        __syncthreads();
        mma_stage(sb + (kc & 1) * STAGE_B, lane, wm, wn, acc);
        __syncthreads();
    }
}

__global__ __launch_bounds__(256)
void gemm_qkv_mma()
{
    extern __shared__ char smem[];
    const uint32_t sb = smem_u32(smem);
    const int tid = threadIdx.x;
    const int z  = blockIdx.z;
    const int m0 = blockIdx.y * BM, n0 = blockIdx.x * BN;

    float acc[2][8][4];
#pragma unroll
    for (int a = 0; a < 2; a++)
#pragma unroll
        for (int b = 0; b < 8; b++)
#pragma unroll
            for (int c = 0; c < 4; c++) acc[a][b][c] = 0.f;

    gemm_body<true>(acc, sb, tid, m0, n0, g_Wh[z], g_Wl[z]);

    // epilogue -> head layout g_QKV[z]
    float* __restrict__ Out = g_QKV[z];
    const int lane = tid & 31, wid = tid >> 5;
    const int wm = wid >> 1, wn = wid & 1;
    const int h = (n0 + wn * 64) >> 6;
#pragma unroll
    for (int mt = 0; mt < 2; mt++)
#pragma unroll
        for (int rr = 0; rr < 2; rr++) {
            const int m = m0 + wm * 32 + mt * 16 + rr * 8 + (lane >> 2);
            const int b = m >> 11, s = m & (SEQ - 1);
            float* dst = &Out[(((size_t)b * NUM_HEADS + h) * SEQ + s) * DK];
#pragma unroll
            for (int j = 0; j < 8; j++) {
                const int t = j * 8 + 2 * (lane & 3);
                float2 v = rr == 0 ? make_float2(acc[mt][j][0], acc[mt][j][1])
                                   : make_float2(acc[mt][j][2], acc[mt][j][3]);
                *(float2*)&dst[t] = v;
            }
        }
}

__global__ __launch_bounds__(256)
void gemm_out_mma(float* __restrict__ C)
{
    extern __shared__ char smem[];
    const uint32_t sb = smem_u32(smem);
    const int tid = threadIdx.x;
    const int m0 = blockIdx.y * BM, n0 = blockIdx.x * BN;

    float acc[2][8][4];
#pragma unroll
    for (int a = 0; a < 2; a++)
#pragma unroll
        for (int b = 0; b < 8; b++)
#pragma unroll
            for (int c = 0; c < 4; c++) acc[a][b][c] = 0.f;

    gemm_body<false>(acc, sb, tid, m0, n0, g_Wh[3], g_Wl[3]);

    const int lane = tid & 31, wid = tid >> 5;
    const int wm = wid >> 1, wn = wid & 1;
#pragma unroll
    for (int mt = 0; mt < 2; mt++)
#pragma unroll
        for (int rr = 0; rr < 2; rr++) {
            const int m = m0 + wm * 32 + mt * 16 + rr * 8 + (lane >> 2);
            float* dst = &C[(size_t)m * D_MODEL + n0 + wn * 64];
#pragma unroll
            for (int j = 0; j < 8; j++) {
                const int t = j * 8 + 2 * (lane & 3);
                float2 v = rr == 0 ? make_float2(acc[mt][j][0], acc[mt][j][1])
                                   : make_float2(acc[mt][j][2], acc[mt][j][3]);
                *(float2*)&dst[t] = v;
            }
        }
}

// =================================================================
// Flash attention (fp32 FFMA2, causal). Epilogue now emits split bf16.
// =================================================================
#define QT 128
#define KT 64
#define QSTR 65
#define KSTR 68
#define ATTN_SMEM_FLOATS (QT * QSTR + DK * KSTR + KT * DK)
#define ATTN_SMEM_BYTES  (ATTN_SMEM_FLOATS * 4)

__global__ __launch_bounds__(QT, 3)
void attn_kernel()
{
    extern __shared__ float smemf[];
    float* Qs  = smemf;
    float* Kst = smemf + QT * QSTR;
    float* Vs  = Kst + DK * KSTR;

    const int tid  = threadIdx.x;
    const int head = blockIdx.y;
    const int q0   = (gridDim.x - 1 - blockIdx.x) * QT;
    const int q    = q0 + tid;

    const float* Qg = g_QKV[0] + (size_t)head * SEQ * DK;
    const float* Kg = g_QKV[1] + (size_t)head * SEQ * DK;
    const float* Vg = g_QKV[2] + (size_t)head * SEQ * DK;

    {
        const float4* src = (const float4*)(Qg + (size_t)q0 * DK);
#pragma unroll
        for (int i = 0; i < 16; i++) {
            const int e   = i * QT + tid;
            const int row = e >> 4;
            const int c   = (e & 15) << 2;
            float4 v = src[e];
            float* p = &Qs[row * QSTR + c];
            p[0] = v.x; p[1] = v.y; p[2] = v.z; p[3] = v.w;
        }
    }

    float mrun = -1e30f, lrun = 0.f;
    u64 o2[32];
#pragma unroll
    for (int d = 0; d < 32; d++) o2[d] = 0ull;

    const int ktiles = (q0 >> 6) + 2;
    for (int kt = 0; kt < ktiles; kt++) {
        const int k0 = kt * KT;
        __syncthreads();
        {
            const float4* ksrc = (const float4*)(Kg + (size_t)k0 * DK);
            const float4* vsrc = (const float4*)(Vg + (size_t)k0 * DK);
#pragma unroll
            for (int i = 0; i < 8; i++) {
                const int e  = i * QT + tid;
                const int j  = e >> 4;
                const int d0 = (e & 15) << 2;
                float4 kv = ksrc[e];
                Kst[(d0 + 0) * KSTR + j] = kv.x;
                Kst[(d0 + 1) * KSTR + j] = kv.y;
                Kst[(d0 + 2) * KSTR + j] = kv.z;
                Kst[(d0 + 3) * KSTR + j] = kv.w;
                ((float4*)Vs)[e] = vsrc[e];
            }
        }
        __syncthreads();

        u64 s2[32];
#pragma unroll
        for (int j = 0; j < 32; j++) s2[j] = 0ull;
#pragma unroll 4
        for (int d = 0; d < DK; d++) {
            const u64 q2 = rep2(Qs[tid * QSTR + d]);
            const ulonglong2* krow = (const ulonglong2*)&Kst[d * KSTR];
#pragma unroll
            for (int j4 = 0; j4 < 16; j4++) {
                ulonglong2 kk = krow[j4];
                fma2(s2[2 * j4],     q2, kk.x);
                fma2(s2[2 * j4 + 1], q2, kk.y);
            }
        }

        float s[KT];
        float mt = mrun;
#pragma unroll
        for (int j2 = 0; j2 < 32; j2++) {
            float lo, hi;
            unpk2(s2[j2], lo, hi);
            lo *= 0.125f; hi *= 0.125f;
            const int jl = 2 * j2, jh = 2 * j2 + 1;
            lo = (k0 + jl > q) ? -1e30f : lo;
            hi = (k0 + jh > q) ? -1e30f : hi;
            s[jl] = lo; s[jh] = hi;
            mt = fmaxf(mt, fmaxf(lo, hi));
        }

        const float corr = __expf(mrun - mt);
        mrun = mt;
        lrun *= corr;
        const u64 c2 = rep2(corr);
#pragma unroll
        for (int d = 0; d < 32; d++) o2[d] = mul2(o2[d], c2);

#pragma unroll 2
        for (int j = 0; j < KT; j++) {
            const float p = __expf(s[j] - mt);
            lrun += p;
            const u64 p2 = rep2(p);
            const ulonglong2* vrow = (const ulonglong2*)&Vs[j * DK];
#pragma unroll
            for (int d4 = 0; d4 < 16; d4++) {
                ulonglong2 vv = vrow[d4];
                fma2(o2[2 * d4],     p2, vv.x);
                fma2(o2[2 * d4 + 1], p2, vv.y);
            }
        }
    }

    // epilogue: normalize + split to hi/lo bf16 directly
    const float inv = 1.f / lrun;
    __nv_bfloat16* dh = g_Ah + ((size_t)head * SEQ + q) * DK;
    __nv_bfloat16* dl = g_Al + ((size_t)head * SEQ + q) * DK;
#pragma unroll
    for (int d2 = 0; d2 < 32; d2++) {
        float a, b;
        unpk2(o2[d2], a, b);
        a *= inv; b *= inv;
        __nv_bfloat16 ha = __float2bfloat16(a), hb = __float2bfloat16(b);
        __nv_bfloat16 la = __float2bfloat16(a - __bfloat162float(ha));
        __nv_bfloat16 lb = __float2bfloat16(b - __bfloat162float(hb));
        *(__nv_bfloat162*)&dh[2 * d2] = __nv_bfloat162(ha, hb);
        *(__nv_bfloat162*)&dl[2 * d2] = __nv_bfloat162(la, lb);
    }
}

// =================================================================
extern "C" void kernel_launch(void* const* d_in, const int* in_sizes, int n_in,
                              void* d_out, int out_size)
{
    const float* X  = (const float*)d_in[0];
    const float* Wq = (const float*)d_in[1];
    const float* Wk = (const float*)d_in[2];
    const float* Wv = (const float*)d_in[3];
    const float* Wo = (const float*)d_in[4];
    float* out = (float*)d_out;

    cudaFuncSetAttribute(attn_kernel, cudaFuncAttributeMaxDynamicSharedMemorySize, ATTN_SMEM_BYTES);
    cudaFuncSetAttribute(gemm_qkv_mma, cudaFuncAttributeMaxDynamicSharedMemorySize, GEMM_SMEM);
    cudaFuncSetAttribute(gemm_out_mma, cudaFuncAttributeMaxDynamicSharedMemorySize, GEMM_SMEM);

    void *xh, *xl, *wh, *wl;
    cudaGetSymbolAddress(&xh, g_Xh);  cudaGetSymbolAddress(&xl, g_Xl);
    cudaGetSymbolAddress(&wh, g_Wh);  cudaGetSymbolAddress(&wl, g_Wl);

    const int xn4 = M_TOTAL * D_MODEL / 4;
    const int wn4 = D_MODEL * D_MODEL / 4;
    const size_t wstride = (size_t)D_MODEL * D_MODEL;

    cvt_kernel<<<(xn4 + 255) / 256, 256>>>(X, (__nv_bfloat16*)xh, (__nv_bfloat16*)xl, xn4);
    cvt_kernel<<<(wn4 + 255) / 256, 256>>>(Wq, (__nv_bfloat16*)wh + 0 * wstride, (__nv_bfloat16*)wl + 0 * wstride, wn4);
    cvt_kernel<<<(wn4 + 255) / 256, 256>>>(Wk, (__nv_bfloat16*)wh + 1 * wstride, (__nv_bfloat16*)wl + 1 * wstride, wn4);
    cvt_kernel<<<(wn4 + 255) / 256, 256>>>(Wv, (__nv_bfloat16*)wh + 2 * wstride, (__nv_bfloat16*)wl + 2 * wstride, wn4);
    cvt_kernel<<<(wn4 + 255) / 256, 256>>>(Wo, (__nv_bfloat16*)wh + 3 * wstride, (__nv_bfloat16*)wl + 3 * wstride, wn4);

    dim3 gProj(D_MODEL / BN, M_TOTAL / BM, 3);     // (8, 32, 3)
    gemm_qkv_mma<<<gProj, 256, GEMM_SMEM>>>();

    dim3 gAttn(SEQ / QT, HEADS_TOT);               // (16, 32)
    attn_kernel<<<gAttn, QT, ATTN_SMEM_BYTES>>>();

    dim3 gOut(D_MODEL / BN, M_TOTAL / BM);         // (8, 32)
    gemm_out_mma<<<gOut, 256, GEMM_SMEM>>>(out);
}

// round 5
// speedup vs baseline: 4.0151x; 1.9567x over previous
#include <cuda_runtime.h>
#include <cuda_bf16.h>
#include <cstdint>
#include <math.h>

#define D_MODEL   1024
#define NUM_HEADS 16
#define DK        64
#define BATCH     2
#define SEQ       2048
#define M_TOTAL   (BATCH * SEQ)          // 4096
#define HEADS_TOT (BATCH * NUM_HEADS)    // 32

// log2(e)/sqrt(64) folded into Q
#define QSCALE 0.18033688011112042f

// ---------------- scratch (no cudaMalloc allowed) ----------------
__device__ __nv_bfloat16 g_Xh[(size_t)M_TOTAL * D_MODEL];
__device__ __nv_bfloat16 g_Xl[(size_t)M_TOTAL * D_MODEL];
__device__ __nv_bfloat16 g_Wh[4][(size_t)D_MODEL * D_MODEL];
__device__ __nv_bfloat16 g_Wl[4][(size_t)D_MODEL * D_MODEL];
// projections, split bf16: Q scaled, K normal [head][s][d]; V transposed [head][d][s]
__device__ __nv_bfloat16 g_Qh[(size_t)HEADS_TOT * SEQ * DK];
__device__ __nv_bfloat16 g_Ql[(size_t)HEADS_TOT * SEQ * DK];
__device__ __nv_bfloat16 g_Kh[(size_t)HEADS_TOT * SEQ * DK];
__device__ __nv_bfloat16 g_Kl[(size_t)HEADS_TOT * SEQ * DK];
__device__ __nv_bfloat16 g_Vth[(size_t)HEADS_TOT * DK * SEQ];
__device__ __nv_bfloat16 g_Vtl[(size_t)HEADS_TOT * DK * SEQ];
// attention output, split bf16 [head][s][d]
__device__ __nv_bfloat16 g_Ah[(size_t)HEADS_TOT * SEQ * DK];
__device__ __nv_bfloat16 g_Al[(size_t)HEADS_TOT * SEQ * DK];

// ---------------- ptx helpers ----------------
__device__ __forceinline__ uint32_t smem_u32(const void* p) {
    uint32_t a;
    asm("{ .reg .u64 t; cvta.to.shared.u64 t, %1; cvt.u32.u64 %0, t; }" : "=r"(a) : "l"(p));
    return a;
}
__device__ __forceinline__ void cp16(uint32_t dst, const void* src) {
    asm volatile("cp.async.cg.shared.global [%0], [%1], 16;" :: "r"(dst), "l"(src));
}
#define CP_COMMIT() asm volatile("cp.async.commit_group;" ::: "memory")
#define CP_WAIT(n)  asm volatile("cp.async.wait_group %0;" :: "n"(n) : "memory")

__device__ __forceinline__ void ldsm4(uint32_t& r0, uint32_t& r1, uint32_t& r2, uint32_t& r3,
                                      uint32_t addr) {
    asm volatile("ldmatrix.sync.aligned.m8n8.x4.shared.b16 {%0,%1,%2,%3}, [%4];"
                 : "=r"(r0), "=r"(r1), "=r"(r2), "=r"(r3) : "r"(addr));
}
__device__ __forceinline__ void mma16816(float* d, const uint32_t* a, const uint32_t* b) {
    asm volatile("mma.sync.aligned.m16n8k16.row.col.f32.bf16.bf16.f32 "
        "{%0,%1,%2,%3}, {%4,%5,%6,%7}, {%8,%9}, {%0,%1,%2,%3};"
        : "+f"(d[0]), "+f"(d[1]), "+f"(d[2]), "+f"(d[3])
        : "r"(a[0]), "r"(a[1]), "r"(a[2]), "r"(a[3]), "r"(b[0]), "r"(b[1]));
}
// pack (x -> lo half, y -> hi half) with hi/lo residual split
__device__ __forceinline__ void split2(float x, float y, uint32_t& hi, uint32_t& lo) {
    uint32_t h;
    asm("cvt.rn.bf16x2.f32 %0, %1, %2;" : "=r"(h) : "f"(y), "f"(x));
    float hx = __uint_as_float(h << 16);
    float hy = __uint_as_float(h & 0xffff0000u);
    float lx = x - hx, ly = y - hy;
    asm("cvt.rn.bf16x2.f32 %0, %1, %2;" : "=r"(lo) : "f"(ly), "f"(lx));
    hi = h;
}
__device__ __forceinline__ float ex2f(float x) {
    float r; asm("ex2.approx.f32 %0, %1;" : "=f"(r) : "f"(x)); return r;
}
__device__ __forceinline__ float rmax4(float v) {
    v = fmaxf(v, __shfl_xor_sync(0xffffffffu, v, 1));
    v = fmaxf(v, __shfl_xor_sync(0xffffffffu, v, 2));
    return v;
}
__device__ __forceinline__ float rsum4(float v) {
    v += __shfl_xor_sync(0xffffffffu, v, 1);
    v += __shfl_xor_sync(0xffffffffu, v, 2);
    return v;
}

// =================================================================
// fp32 -> (hi, lo) bf16 split, elementwise
// =================================================================
__global__ __launch_bounds__(256)
void cvt_kernel(const float* __restrict__ src,
                __nv_bfloat16* __restrict__ hi,
                __nv_bfloat16* __restrict__ lo, int n4)
{
    int i = blockIdx.x * 256 + threadIdx.x;
    if (i >= n4) return;
    float4 v = ((const float4*)src)[i];
    uint32_t h0, l0, h1, l1;
    split2(v.x, v.y, h0, l0);
    split2(v.z, v.w, h1, l1);
    ((uint2*)hi)[i] = make_uint2(h0, h1);
    ((uint2*)lo)[i] = make_uint2(l0, l1);
}

// =================================================================
// split-bf16 HMMA GEMM: block 128x128, BK=32, 8 warps (4x2), warp 32x64.
// =================================================================
#define BM 128
#define BN 128
#define BK 32
#define SSTR   40
#define TILE_B (BM * SSTR * 2)
#define STAGE_B (4 * TILE_B)
#define GEMM_SMEM (2 * STAGE_B)          // 81920 B

template<bool QKV>
__device__ __forceinline__ void issue_copies(uint32_t stage_sb, int tid, int m0, int n0, int kc,
                                             const __nv_bfloat16* __restrict__ Wh,
                                             const __nv_bfloat16* __restrict__ Wl)
{
    const int k0 = kc * BK;
#pragma unroll
    for (int o = 0; o < 8; o++) {
        const int e    = o * 256 + tid;
        const int tile = e >> 9;
        const int idx  = e & 511;
        const int r = idx >> 2, c = idx & 3;
        const uint32_t dst = stage_sb + tile * TILE_B + r * (SSTR * 2) + c * 16;
        const __nv_bfloat16* src;
        if (tile < 2) {
            size_t ai;
            if (QKV) {
                ai = (size_t)(m0 + r) * D_MODEL + k0 + c * 8;
            } else {
                const int m = m0 + r;
                ai = (((size_t)(m >> 11) * NUM_HEADS + (k0 >> 6)) * SEQ + (m & (SEQ - 1))) * DK
                     + (k0 & 63) + c * 8;
            }
            src = (tile == 0 ? (QKV ? g_Xh : g_Ah) : (QKV ? g_Xl : g_Al)) + ai;
        } else {
            const size_t bi = (size_t)(n0 + r) * D_MODEL + k0 + c * 8;
            src = (tile == 2 ? Wh : Wl) + bi;
        }
        cp16(dst, src);
    }
}

__device__ __forceinline__ void mma_stage(uint32_t Abase, int lane, int wm, int wn,
                                          float acc[2][8][4])
{
#pragma unroll
    for (int h = 0; h < 2; h++) {
        uint32_t ah[2][4], al[2][4];
#pragma unroll
        for (int mt = 0; mt < 2; mt++) {
            const uint32_t addr = Abase
                + (uint32_t)(wm * 32 + mt * 16 + (lane & 15)) * (SSTR * 2)
                + h * 32 + ((lane >> 4) << 4);
            ldsm4(ah[mt][0], ah[mt][1], ah[mt][2], ah[mt][3], addr);
            ldsm4(al[mt][0], al[mt][1], al[mt][2], al[mt][3], addr + TILE_B);
        }
        uint32_t bh[4][4], bl[4][4];
#pragma unroll
        for (int nt = 0; nt < 4; nt++) {
            const uint32_t addr = Abase + 2 * TILE_B
                + (uint32_t)(wn * 64 + nt * 16 + (lane & 7) + ((lane >> 4) << 3)) * (SSTR * 2)
                + h * 32 + (((lane >> 3) & 1) << 4);
            ldsm4(bh[nt][0], bh[nt][1], bh[nt][2], bh[nt][3], addr);
            ldsm4(bl[nt][0], bl[nt][1], bl[nt][2], bl[nt][3], addr + TILE_B);
        }
#pragma unroll
        for (int mt = 0; mt < 2; mt++)
#pragma unroll
            for (int nt = 0; nt < 4; nt++) {
                mma16816(acc[mt][2 * nt],     ah[mt], &bh[nt][0]);
                mma16816(acc[mt][2 * nt + 1], ah[mt], &bh[nt][2]);
                mma16816(acc[mt][2 * nt],     ah[mt], &bl[nt][0]);
                mma16816(acc[mt][2 * nt + 1], ah[mt], &bl[nt][2]);
                mma16816(acc[mt][2 * nt],     al[mt], &bh[nt][0]);
                mma16816(acc[mt][2 * nt + 1], al[mt], &bh[nt][2]);
            }
    }
}

template<bool QKV>
__device__ __forceinline__ void gemm_body(float acc[2][8][4], uint32_t sb, int tid,
                                          int m0, int n0,
                                          const __nv_bfloat16* __restrict__ Wh,
                                          const __nv_bfloat16* __restrict__ Wl)
{
    const int lane = tid & 31, wid = tid >> 5;
    const int wm = wid >> 1, wn = wid & 1;
    const int NKC = D_MODEL / BK;

    issue_copies<QKV>(sb, tid, m0, n0, 0, Wh, Wl);
    CP_COMMIT();
    for (int kc = 0; kc < NKC; kc++) {
        if (kc + 1 < NKC) {
            issue_copies<QKV>(sb + ((kc + 1) & 1) * STAGE_B, tid, m0, n0, kc + 1, Wh, Wl);
            CP_COMMIT();
            CP_WAIT(1);
        } else {
            CP_WAIT(0);
        }
        __syncthreads();
        mma_stage(sb + (kc & 1) * STAGE_B, lane, wm, wn, acc);
        __syncthreads();
    }
}

// QKV projection: writes split bf16 directly (Q scaled; V transposed).
__global__ __launch_bounds__(256)
void gemm_qkv_mma()
{
    extern __shared__ char smem[];
    const uint32_t sb = smem_u32(smem);
    const int tid = threadIdx.x;
    const int z  = blockIdx.z;
    const int m0 = blockIdx.y * BM, n0 = blockIdx.x * BN;

    float acc[2][8][4];
#pragma unroll
    for (int a = 0; a < 2; a++)
#pragma unroll
        for (int b = 0; b < 8; b++)
#pragma unroll
            for (int c = 0; c < 4; c++) acc[a][b][c] = 0.f;

    gemm_body<true>(acc, sb, tid, m0, n0, g_Wh[z], g_Wl[z]);

    const float scale = (z == 0) ? QSCALE : 1.0f;
    const int lane = tid & 31, wid = tid >> 5;
    const int wm = wid >> 1, wn = wid & 1;
    const int h = ((n0 + wn * 64) >> 6);
#pragma unroll
    for (int mt = 0; mt < 2; mt++)
#pragma unroll
        for (int rr = 0; rr < 2; rr++) {
            const int m = m0 + wm * 32 + mt * 16 + rr * 8 + (lane >> 2);
            const int b = m >> 11, s = m & (SEQ - 1);
            const int head = b * NUM_HEADS + h;
#pragma unroll
            for (int j = 0; j < 8; j++) {
                const int t = j * 8 + 2 * (lane & 3);
                const float x = acc[mt][j][2 * rr] * scale;
                const float y = acc[mt][j][2 * rr + 1] * scale;
                if (z == 2) {
                    // transposed V: [head][d][s]
                    const size_t base = ((size_t)head * DK + t) * SEQ + s;
                    __nv_bfloat16 hx = __float2bfloat16(x);
                    __nv_bfloat16 hy = __float2bfloat16(y);
                    g_Vth[base]       = hx;
                    g_Vtl[base]       = __float2bfloat16(x - __bfloat162float(hx));
                    g_Vth[base + SEQ] = hy;
                    g_Vtl[base + SEQ] = __float2bfloat16(y - __bfloat162float(hy));
                } else {
                    uint32_t hi, lo;
                    split2(x, y, hi, lo);
                    const size_t base = ((size_t)head * SEQ + s) * DK + t;
                    if (z == 0) {
                        *(uint32_t*)&g_Qh[base] = hi;
                        *(uint32_t*)&g_Ql[base] = lo;
                    } else {
                        *(uint32_t*)&g_Kh[base] = hi;
                        *(uint32_t*)&g_Kl[base] = lo;
                    }
                }
            }
        }
}

// Output projection: gathers split attn output, writes fp32 d_out.
__global__ __launch_bounds__(256)
void gemm_out_mma(float* __restrict__ C)
{
    extern __shared__ char smem[];
    const uint32_t sb = smem_u32(smem);
    const int tid = threadIdx.x;
    const int m0 = blockIdx.y * BM, n0 = blockIdx.x * BN;

    float acc[2][8][4];
#pragma unroll
    for (int a = 0; a < 2; a++)
#pragma unroll
        for (int b = 0; b < 8; b++)
#pragma unroll
            for (int c = 0; c < 4; c++) acc[a][b][c] = 0.f;

    gemm_body<false>(acc, sb, tid, m0, n0, g_Wh[3], g_Wl[3]);

    const int lane = tid & 31, wid = tid >> 5;
    const int wm = wid >> 1, wn = wid & 1;
#pragma unroll
    for (int mt = 0; mt < 2; mt++)
#pragma unroll
        for (int rr = 0; rr < 2; rr++) {
            const int m = m0 + wm * 32 + mt * 16 + rr * 8 + (lane >> 2);
            float* dst = &C[(size_t)m * D_MODEL + n0 + wn * 64];
#pragma unroll
            for (int j = 0; j < 8; j++) {
                const int t = j * 8 + 2 * (lane & 3);
                float2 v = rr == 0 ? make_float2(acc[mt][j][0], acc[mt][j][1])
                                   : make_float2(acc[mt][j][2], acc[mt][j][3]);
                *(float2*)&dst[t] = v;
            }
        }
}

// =================================================================
// Flash attention, split-bf16 HMMA. Block: 256 thr (8 warps x 16 q rows).
// KT=64. K tile [j][d]; V tile pre-transposed [d][j]. Q frags resident.
// Scores already in log2 units (QSCALE folded into Q).
// =================================================================
#define AT_SSTR  72                      // bf16 per row (144 B) — ldsm conflict-free
#define AT_ROWB  (AT_SSTR * 2)           // 144
#define AT_TILEB (64 * AT_ROWB)          // 9216
#define ATTN_SMEM (4 * AT_TILEB)         // 36864

__global__ __launch_bounds__(256)
void attn_mma()
{
    extern __shared__ char smem[];
    const uint32_t sb = smem_u32(smem);
    const int tid = threadIdx.x, lane = tid & 31, w = tid >> 5;
    const int head = blockIdx.y;
    const int q0 = (int)(gridDim.x - 1 - blockIdx.x) * 128;  // heavy blocks first
    const int qwb = q0 + w * 16;

    // ---- stage Q tile (hi at sb, lo at sb + 2*AT_TILEB), load A frags ----
    {
        const __nv_bfloat16* Qh = g_Qh + ((size_t)head * SEQ + q0) * DK;
        const __nv_bfloat16* Ql = g_Ql + ((size_t)head * SEQ + q0) * DK;
#pragma unroll
        for (int i = 0; i < 8; i++) {
            const int e = i * 256 + tid;        // 0..2047
            const int half = e >> 10;
            const int idx = e & 1023;
            const int row = idx >> 3, c = idx & 7;
            const uint32_t dst = sb + half * (2 * AT_TILEB) + row * AT_ROWB + c * 16;
            const __nv_bfloat16* src = (half ? Ql : Qh) + (size_t)row * DK + c * 8;
            cp16(dst, src);
        }
        CP_COMMIT(); CP_WAIT(0);
        __syncthreads();
    }
    uint32_t qh[4][4], ql[4][4];
#pragma unroll
    for (int kc = 0; kc < 4; kc++) {
        const uint32_t a = sb + (uint32_t)(w * 16 + (lane & 15)) * AT_ROWB
                         + kc * 32 + ((lane >> 4) << 4);
        ldsm4(qh[kc][0], qh[kc][1], qh[kc][2], qh[kc][3], a);
        ldsm4(ql[kc][0], ql[kc][1], ql[kc][2], ql[kc][3], a + 2 * AT_TILEB);
    }
    __syncthreads();

    float o[8][4];
#pragma unroll
    for (int nt = 0; nt < 8; nt++)
#pragma unroll
        for (int r = 0; r < 4; r++) o[nt][r] = 0.f;
    float mrow0 = -1e30f, mrow1 = -1e30f, lrow0 = 0.f, lrow1 = 0.f;

    const int ktiles = (q0 >> 6) + 2;
    for (int t = 0; t < ktiles; t++) {
        const int k0 = t * 64;
        // ---- load K (hi, lo) and Vt (hi, lo) tiles ----
#pragma unroll
        for (int i = 0; i < 8; i++) {
            const int e = i * 256 + tid;
            const int arr = e >> 9, idx = e & 511;
            const int row = idx >> 3, c = idx & 7;
            const uint32_t dst = sb + arr * AT_TILEB + row * AT_ROWB + c * 16;
            const __nv_bfloat16* src;
            if (arr == 0)      src = g_Kh  + ((size_t)head * SEQ + k0 + row) * DK + c * 8;
            else if (arr == 1) src = g_Kl  + ((size_t)head * SEQ + k0 + row) * DK + c * 8;
            else if (arr == 2) src = g_Vth + ((size_t)head * DK + row) * SEQ + k0 + c * 8;
            else               src = g_Vtl + ((size_t)head * DK + row) * SEQ + k0 + c * 8;
            cp16(dst, src);
        }
        CP_COMMIT(); CP_WAIT(0);
        __syncthreads();

        // ---- QK^T: sc[nt] covers keys nt*8..nt*8+7 ----
        float sc[8][4];
#pragma unroll
        for (int nt = 0; nt < 8; nt++)
#pragma unroll
            for (int r = 0; r < 4; r++) sc[nt][r] = 0.f;
#pragma unroll
        for (int kc = 0; kc < 4; kc++)
#pragma unroll
            for (int g = 0; g < 4; g++) {
                uint32_t kh[4], kl[4];
                const uint32_t ad = sb + (uint32_t)(g * 16 + (lane & 7) + ((lane >> 4) << 3)) * AT_ROWB
                                  + kc * 32 + (((lane >> 3) & 1) << 4);
                ldsm4(kh[0], kh[1], kh[2], kh[3], ad);
                ldsm4(kl[0], kl[1], kl[2], kl[3], ad + AT_TILEB);
                mma16816(sc[2 * g],     qh[kc], &kh[0]);
                mma16816(sc[2 * g + 1], qh[kc], &kh[2]);
                mma16816(sc[2 * g],     qh[kc], &kl[0]);
                mma16816(sc[2 * g + 1], qh[kc], &kl[2]);
                mma16816(sc[2 * g],     ql[kc], &kh[0]);
                mma16816(sc[2 * g + 1], ql[kc], &kh[2]);
            }

        // ---- causal mask (diagonal tiles only) ----
        if (k0 + 63 > qwb) {
            const int r0 = qwb + (lane >> 2);
            const int kb = k0 + 2 * (lane & 3);
#pragma unroll
            for (int nt = 0; nt < 8; nt++) {
                const int kk = kb + nt * 8;
                if (kk     > r0)     sc[nt][0] = -1e30f;
                if (kk + 1 > r0)     sc[nt][1] = -1e30f;
                if (kk     > r0 + 8) sc[nt][2] = -1e30f;
                if (kk + 1 > r0 + 8) sc[nt][3] = -1e30f;
            }
        }

        // ---- online softmax (base 2) ----
        float mx0 = sc[0][0], mx1 = sc[0][2];
#pragma unroll
        for (int nt = 0; nt < 8; nt++) {
            mx0 = fmaxf(mx0, fmaxf(sc[nt][0], sc[nt][1]));
            mx1 = fmaxf(mx1, fmaxf(sc[nt][2], sc[nt][3]));
        }
        mx0 = rmax4(mx0); mx1 = rmax4(mx1);
        const float mn0 = fmaxf(mrow0, mx0), mn1 = fmaxf(mrow1, mx1);
        const float c0 = ex2f(mrow0 - mn0), c1 = ex2f(mrow1 - mn1);
        mrow0 = mn0; mrow1 = mn1;
        float s0 = 0.f, s1 = 0.f;
#pragma unroll
        for (int nt = 0; nt < 8; nt++) {
            sc[nt][0] = ex2f(sc[nt][0] - mn0); s0 += sc[nt][0];
            sc[nt][1] = ex2f(sc[nt][1] - mn0); s0 += sc[nt][1];
            sc[nt][2] = ex2f(sc[nt][2] - mn1); s1 += sc[nt][2];
            sc[nt][3] = ex2f(sc[nt][3] - mn1); s1 += sc[nt][3];
        }
        s0 = rsum4(s0); s1 = rsum4(s1);
        lrow0 = lrow0 * c0 + s0;
        lrow1 = lrow1 * c1 + s1;
#pragma unroll
        for (int nt = 0; nt < 8; nt++) {
            o[nt][0] *= c0; o[nt][1] *= c0;
            o[nt][2] *= c1; o[nt][3] *= c1;
        }

        // ---- P @ V: A = P frags (from sc), B = Vt ----
#pragma unroll
        for (int kc = 0; kc < 4; kc++) {
            uint32_t ph[4], pl[4];
            split2(sc[2 * kc][0],     sc[2 * kc][1],     ph[0], pl[0]);
            split2(sc[2 * kc][2],     sc[2 * kc][3],     ph[1], pl[1]);
            split2(sc[2 * kc + 1][0], sc[2 * kc + 1][1], ph[2], pl[2]);
            split2(sc[2 * kc + 1][2], sc[2 * kc + 1][3], ph[3], pl[3]);
#pragma unroll
            for (int g = 0; g < 4; g++) {
                uint32_t vh[4], vl[4];
                const uint32_t ad = sb + 2 * AT_TILEB
                    + (uint32_t)(g * 16 + (lane & 7) + ((lane >> 4) << 3)) * AT_ROWB
                    + kc * 32 + (((lane >> 3) & 1) << 4);
                ldsm4(vh[0], vh[1], vh[2], vh[3], ad);
                ldsm4(vl[0], vl[1], vl[2], vl[3], ad + AT_TILEB);
                mma16816(o[2 * g],     ph, &vh[0]);
                mma16816(o[2 * g + 1], ph, &vh[2]);
                mma16816(o[2 * g],     ph, &vl[0]);
                mma16816(o[2 * g + 1], ph, &vl[2]);
                mma16816(o[2 * g],     pl, &vh[0]);
                mma16816(o[2 * g + 1], pl, &vh[2]);
            }
        }
        __syncthreads();   // before next tile overwrites smem
    }

    // ---- epilogue: normalize, split, store ----
    const float i0 = 1.f / lrow0, i1 = 1.f / lrow1;
    const int r0 = qwb + (lane >> 2);
    const int dbase = 2 * (lane & 3);
#pragma unroll
    for (int nt = 0; nt < 8; nt++) {
        const int d = nt * 8 + dbase;
        uint32_t hi, lo;
        split2(o[nt][0] * i0, o[nt][1] * i0, hi, lo);
        size_t base = ((size_t)head * SEQ + r0) * DK + d;
        *(uint32_t*)&g_Ah[base] = hi;
        *(uint32_t*)&g_Al[base] = lo;
        split2(o[nt][2] * i1, o[nt][3] * i1, hi, lo);
        base = ((size_t)head * SEQ + r0 + 8) * DK + d;
        *(uint32_t*)&g_Ah[base] = hi;
        *(uint32_t*)&g_Al[base] = lo;
    }
}

// =================================================================
extern "C" void kernel_launch(void* const* d_in, const int* in_sizes, int n_in,
                              void* d_out, int out_size)
{
    const float* X  = (const float*)d_in[0];
    const float* Wq = (const float*)d_in[1];
    const float* Wk = (const float*)d_in[2];
    const float* Wv = (const float*)d_in[3];
    const float* Wo = (const float*)d_in[4];
    float* out = (float*)d_out;

    cudaFuncSetAttribute(gemm_qkv_mma, cudaFuncAttributeMaxDynamicSharedMemorySize, GEMM_SMEM);
    cudaFuncSetAttribute(gemm_out_mma, cudaFuncAttributeMaxDynamicSharedMemorySize, GEMM_SMEM);
    cudaFuncSetAttribute(attn_mma,     cudaFuncAttributeMaxDynamicSharedMemorySize, ATTN_SMEM);

    void *xh, *xl, *wh, *wl;
    cudaGetSymbolAddress(&xh, g_Xh);  cudaGetSymbolAddress(&xl, g_Xl);
    cudaGetSymbolAddress(&wh, g_Wh);  cudaGetSymbolAddress(&wl, g_Wl);

    const int xn4 = M_TOTAL * D_MODEL / 4;
    const int wn4 = D_MODEL * D_MODEL / 4;
    const size_t wstride = (size_t)D_MODEL * D_MODEL;

    cvt_kernel<<<(xn4 + 255) / 256, 256>>>(X, (__nv_bfloat16*)xh, (__nv_bfloat16*)xl, xn4);
    cvt_kernel<<<(wn4 + 255) / 256, 256>>>(Wq, (__nv_bfloat16*)wh + 0 * wstride, (__nv_bfloat16*)wl + 0 * wstride, wn4);
    cvt_kernel<<<(wn4 + 255) / 256, 256>>>(Wk, (__nv_bfloat16*)wh + 1 * wstride, (__nv_bfloat16*)wl + 1 * wstride, wn4);
    cvt_kernel<<<(wn4 + 255) / 256, 256>>>(Wv, (__nv_bfloat16*)wh + 2 * wstride, (__nv_bfloat16*)wl + 2 * wstride, wn4);
    cvt_kernel<<<(wn4 + 255) / 256, 256>>>(Wo, (__nv_bfloat16*)wh + 3 * wstride, (__nv_bfloat16*)wl + 3 * wstride, wn4);

    dim3 gProj(D_MODEL / BN, M_TOTAL / BM, 3);     // (8, 32, 3)
    gemm_qkv_mma<<<gProj, 256, GEMM_SMEM>>>();

    dim3 gAttn(SEQ / 128, HEADS_TOT);              // (16, 32)
    attn_mma<<<gAttn, 256, ATTN_SMEM>>>();

    dim3 gOut(D_MODEL / BN, M_TOTAL / BM);         // (8, 32)
    gemm_out_mma<<<gOut, 256, GEMM_SMEM>>>(out);
}

// round 7
// speedup vs baseline: 4.2214x; 1.0514x over previous
#include <cuda_runtime.h>
#include <cuda_bf16.h>
#include <cstdint>
#include <math.h>

#define D_MODEL   1024
#define NUM_HEADS 16
#define DK        64
#define BATCH     2
#define SEQ       2048
#define M_TOTAL   (BATCH * SEQ)          // 4096
#define HEADS_TOT (BATCH * NUM_HEADS)    // 32

// log2(e)/sqrt(64) folded into Q
#define QSCALE 0.18033688011112042f

// ---------------- scratch (no cudaMalloc allowed) ----------------
__device__ __nv_bfloat16 g_Xh[(size_t)M_TOTAL * D_MODEL];
__device__ __nv_bfloat16 g_Xl[(size_t)M_TOTAL * D_MODEL];
__device__ __nv_bfloat16 g_Wh[4][(size_t)D_MODEL * D_MODEL];
__device__ __nv_bfloat16 g_Wl[4][(size_t)D_MODEL * D_MODEL];
__device__ __nv_bfloat16 g_Qh[(size_t)HEADS_TOT * SEQ * DK];
__device__ __nv_bfloat16 g_Ql[(size_t)HEADS_TOT * SEQ * DK];
__device__ __nv_bfloat16 g_Kh[(size_t)HEADS_TOT * SEQ * DK];
__device__ __nv_bfloat16 g_Kl[(size_t)HEADS_TOT * SEQ * DK];
__device__ __nv_bfloat16 g_Vth[(size_t)HEADS_TOT * DK * SEQ];
__device__ __nv_bfloat16 g_Vtl[(size_t)HEADS_TOT * DK * SEQ];
__device__ __nv_bfloat16 g_Ah[(size_t)HEADS_TOT * SEQ * DK];
__device__ __nv_bfloat16 g_Al[(size_t)HEADS_TOT * SEQ * DK];

// ---------------- ptx helpers ----------------
__device__ __forceinline__ uint32_t smem_u32(const void* p) {
    uint32_t a;
    asm("{ .reg .u64 t; cvta.to.shared.u64 t, %1; cvt.u32.u64 %0, t; }" : "=r"(a) : "l"(p));
    return a;
}
__device__ __forceinline__ void cp16(uint32_t dst, const void* src) {
    asm volatile("cp.async.cg.shared.global [%0], [%1], 16;" :: "r"(dst), "l"(src));
}
#define CP_COMMIT() asm volatile("cp.async.commit_group;" ::: "memory")
#define CP_WAIT(n)  asm volatile("cp.async.wait_group %0;" :: "n"(n) : "memory")

__device__ __forceinline__ void ldsm4(uint32_t& r0, uint32_t& r1, uint32_t& r2, uint32_t& r3,
                                      uint32_t addr) {
    asm volatile("ldmatrix.sync.aligned.m8n8.x4.shared.b16 {%0,%1,%2,%3}, [%4];"
                 : "=r"(r0), "=r"(r1), "=r"(r2), "=r"(r3) : "r"(addr));
}
__device__ __forceinline__ void mma16816(float* d, const uint32_t* a, const uint32_t* b) {
    asm volatile("mma.sync.aligned.m16n8k16.row.col.f32.bf16.bf16.f32 "
        "{%0,%1,%2,%3}, {%4,%5,%6,%7}, {%8,%9}, {%0,%1,%2,%3};"
        : "+f"(d[0]), "+f"(d[1]), "+f"(d[2]), "+f"(d[3])
        : "r"(a[0]), "r"(a[1]), "r"(a[2]), "r"(a[3]), "r"(b[0]), "r"(b[1]));
}
__device__ __forceinline__ void split2(float x, float y, uint32_t& hi, uint32_t& lo) {
    uint32_t h;
    asm("cvt.rn.bf16x2.f32 %0, %1, %2;" : "=r"(h) : "f"(y), "f"(x));
    float hx = __uint_as_float(h << 16);
    float hy = __uint_as_float(h & 0xffff0000u);
    float lx = x - hx, ly = y - hy;
    asm("cvt.rn.bf16x2.f32 %0, %1, %2;" : "=r"(lo) : "f"(ly), "f"(lx));
    hi = h;
}
__device__ __forceinline__ float ex2f(float x) {
    float r; asm("ex2.approx.f32 %0, %1;" : "=f"(r) : "f"(x)); return r;
}
__device__ __forceinline__ float rmax4(float v) {
    v = fmaxf(v, __shfl_xor_sync(0xffffffffu, v, 1));
    v = fmaxf(v, __shfl_xor_sync(0xffffffffu, v, 2));
    return v;
}
__device__ __forceinline__ float rsum4(float v) {
    v += __shfl_xor_sync(0xffffffffu, v, 1);
    v += __shfl_xor_sync(0xffffffffu, v, 2);
    return v;
}

// =================================================================
// fused fp32 -> (hi, lo) bf16 split for X + 4 weights (one launch)
// =================================================================
__global__ __launch_bounds__(256)
void cvt_all(const float* __restrict__ X,  const float* __restrict__ Wq,
             const float* __restrict__ Wk, const float* __restrict__ Wv,
             const float* __restrict__ Wo)
{
    const int bid = blockIdx.x;
    const float* src;
    __nv_bfloat16 *hi, *lo;
    int i;
    if (bid < 4096) {
        src = X; hi = g_Xh; lo = g_Xl;
        i = bid * 256 + threadIdx.x;
    } else {
        const int seg = (bid - 4096) >> 10;
        i = ((bid - 4096) & 1023) * 256 + threadIdx.x;
        src = seg == 0 ? Wq : seg == 1 ? Wk : seg == 2 ? Wv : Wo;
        hi = g_Wh[seg]; lo = g_Wl[seg];
    }
    float4 v = ((const float4*)src)[i];
    uint32_t h0, l0, h1, l1;
    split2(v.x, v.y, h0, l0);
    split2(v.z, v.w, h1, l1);
    ((uint2*)hi)[i] = make_uint2(h0, h1);
    ((uint2*)lo)[i] = make_uint2(l0, l1);
}

// =================================================================
// split-bf16 HMMA GEMM: block 128x128, BK=32, 8 warps (4x2), warp 32x64.
// =================================================================
#define BM 128
#define BN 128
#define BK 32
#define SSTR   40
#define TILE_B (BM * SSTR * 2)
#define STAGE_B (4 * TILE_B)
#define GEMM_SMEM (2 * STAGE_B)          // 81920 B

template<bool QKV>
__device__ __forceinline__ void issue_copies(uint32_t stage_sb, int tid, int m0, int n0, int kc,
                                             const __nv_bfloat16* __restrict__ Wh,
                                             const __nv_bfloat16* __restrict__ Wl)
{
    const int k0 = kc * BK;
#pragma unroll
    for (int o = 0; o < 8; o++) {
        const int e    = o * 256 + tid;
        const int tile = e >> 9;
        const int idx  = e & 511;
        const int r = idx >> 2, c = idx & 3;
        const uint32_t dst = stage_sb + tile * TILE_B + r * (SSTR * 2) + c * 16;
        const __nv_bfloat16* src;
        if (tile < 2) {
            size_t ai;
            if (QKV) {
                ai = (size_t)(m0 + r) * D_MODEL + k0 + c * 8;
            } else {
                const int m = m0 + r;
                ai = (((size_t)(m >> 11) * NUM_HEADS + (k0 >> 6)) * SEQ + (m & (SEQ - 1))) * DK
                     + (k0 & 63) + c * 8;
            }
            src = (tile == 0 ? (QKV ? g_Xh : g_Ah) : (QKV ? g_Xl : g_Al)) + ai;
        } else {
            const size_t bi = (size_t)(n0 + r) * D_MODEL + k0 + c * 8;
            src = (tile == 2 ? Wh : Wl) + bi;
        }
        cp16(dst, src);
    }
}

__device__ __forceinline__ void mma_stage(uint32_t Abase, int lane, int wm, int wn,
                                          float acc[2][8][4])
{
#pragma unroll
    for (int h = 0; h < 2; h++) {
        uint32_t ah[2][4], al[2][4];
#pragma unroll
        for (int mt = 0; mt < 2; mt++) {
            const uint32_t addr = Abase
                + (uint32_t)(wm * 32 + mt * 16 + (lane & 15)) * (SSTR * 2)
                + h * 32 + ((lane >> 4) << 4);
            ldsm4(ah[mt][0], ah[mt][1], ah[mt][2], ah[mt][3], addr);
            ldsm4(al[mt][0], al[mt][1], al[mt][2], al[mt][3], addr + TILE_B);
        }
        uint32_t bh[4][4], bl[4][4];
#pragma unroll
        for (int nt = 0; nt < 4; nt++) {
            const uint32_t addr = Abase + 2 * TILE_B
                + (uint32_t)(wn * 64 + nt * 16 + (lane & 7) + ((lane >> 4) << 3)) * (SSTR * 2)
                + h * 32 + (((lane >> 3) & 1) << 4);
            ldsm4(bh[nt][0], bh[nt][1], bh[nt][2], bh[nt][3], addr);
            ldsm4(bl[nt][0], bl[nt][1], bl[nt][2], bl[nt][3], addr + TILE_B);
        }
#pragma unroll
        for (int mt = 0; mt < 2; mt++)
#pragma unroll
            for (int nt = 0; nt < 4; nt++) {
                mma16816(acc[mt][2 * nt],     ah[mt], &bh[nt][0]);
                mma16816(acc[mt][2 * nt + 1], ah[mt], &bh[nt][2]);
                mma16816(acc[mt][2 * nt],     ah[mt], &bl[nt][0]);
                mma16816(acc[mt][2 * nt + 1], ah[mt], &bl[nt][2]);
                mma16816(acc[mt][2 * nt],     al[mt], &bh[nt][0]);
                mma16816(acc[mt][2 * nt + 1], al[mt], &bh[nt][2]);
            }
    }
}

template<bool QKV>
__device__ __forceinline__ void gemm_body(float acc[2][8][4], uint32_t sb, int tid,
                                          int m0, int n0,
                                          const __nv_bfloat16* __restrict__ Wh,
                                          const __nv_bfloat16* __restrict__ Wl)
{
    const int lane = tid & 31, wid = tid >> 5;
    const int wm = wid >> 1, wn = wid & 1;
    const int NKC = D_MODEL / BK;

    issue_copies<QKV>(sb, tid, m0, n0, 0, Wh, Wl);
    CP_COMMIT();
    for (int kc = 0; kc < NKC; kc++) {
        if (kc + 1 < NKC) {
            issue_copies<QKV>(sb + ((kc + 1) & 1) * STAGE_B, tid, m0, n0, kc + 1, Wh, Wl);
            CP_COMMIT();
            CP_WAIT(1);
        } else {
            CP_WAIT(0);
        }
        __syncthreads();
        mma_stage(sb + (kc & 1) * STAGE_B, lane, wm, wn, acc);
        __syncthreads();
    }
}

__global__ __launch_bounds__(256)
void gemm_qkv_mma()
{
    extern __shared__ char smem[];
    const uint32_t sb = smem_u32(smem);
    const int tid = threadIdx.x;
    const int z  = blockIdx.z;
    const int m0 = blockIdx.y * BM, n0 = blockIdx.x * BN;

    float acc[2][8][4];
#pragma unroll
    for (int a = 0; a < 2; a++)
#pragma unroll
        for (int b = 0; b < 8; b++)
#pragma unroll
            for (int c = 0; c < 4; c++) acc[a][b][c] = 0.f;

    gemm_body<true>(acc, sb, tid, m0, n0, g_Wh[z], g_Wl[z]);

    const float scale = (z == 0) ? QSCALE : 1.0f;
    const int lane = tid & 31, wid = tid >> 5;
    const int wm = wid >> 1, wn = wid & 1;
    const int h = ((n0 + wn * 64) >> 6);
#pragma unroll
    for (int mt = 0; mt < 2; mt++)
#pragma unroll
        for (int rr = 0; rr < 2; rr++) {
            const int m = m0 + wm * 32 + mt * 16 + rr * 8 + (lane >> 2);
            const int b = m >> 11, s = m & (SEQ - 1);
            const int head = b * NUM_HEADS + h;
#pragma unroll
            for (int j = 0; j < 8; j++) {
                const int t = j * 8 + 2 * (lane & 3);
                const float x = acc[mt][j][2 * rr] * scale;
                const float y = acc[mt][j][2 * rr + 1] * scale;
                if (z == 2) {
                    const size_t base = ((size_t)head * DK + t) * SEQ + s;
                    __nv_bfloat16 hx = __float2bfloat16(x);
                    __nv_bfloat16 hy = __float2bfloat16(y);
                    g_Vth[base]       = hx;
                    g_Vtl[base]       = __float2bfloat16(x - __bfloat162float(hx));
                    g_Vth[base + SEQ] = hy;
                    g_Vtl[base + SEQ] = __float2bfloat16(y - __bfloat162float(hy));
                } else {
                    uint32_t hi, lo;
                    split2(x, y, hi, lo);
                    const size_t base = ((size_t)head * SEQ + s) * DK + t;
                    if (z == 0) {
                        *(uint32_t*)&g_Qh[base] = hi;
                        *(uint32_t*)&g_Ql[base] = lo;
                    } else {
                        *(uint32_t*)&g_Kh[base] = hi;
                        *(uint32_t*)&g_Kl[base] = lo;
                    }
                }
            }
        }
}

__global__ __launch_bounds__(256)
void gemm_out_mma(float* __restrict__ C)
{
    extern __shared__ char smem[];
    const uint32_t sb = smem_u32(smem);
    const int tid = threadIdx.x;
    const int m0 = blockIdx.y * BM, n0 = blockIdx.x * BN;

    float acc[2][8][4];
#pragma unroll
    for (int a = 0; a < 2; a++)
#pragma unroll
        for (int b = 0; b < 8; b++)
#pragma unroll
            for (int c = 0; c < 4; c++) acc[a][b][c] = 0.f;

    gemm_body<false>(acc, sb, tid, m0, n0, g_Wh[3], g_Wl[3]);

    const int lane = tid & 31, wid = tid >> 5;
    const int wm = wid >> 1, wn = wid & 1;
#pragma unroll
    for (int mt = 0; mt < 2; mt++)
#pragma unroll
        for (int rr = 0; rr < 2; rr++) {
            const int m = m0 + wm * 32 + mt * 16 + rr * 8 + (lane >> 2);
            float* dst = &C[(size_t)m * D_MODEL + n0 + wn * 64];
#pragma unroll
            for (int j = 0; j < 8; j++) {
                const int t = j * 8 + 2 * (lane & 3);
                float2 v = rr == 0 ? make_float2(acc[mt][j][0], acc[mt][j][1])
                                   : make_float2(acc[mt][j][2], acc[mt][j][3]);
                *(float2*)&dst[t] = v;
            }
        }
}

// =================================================================
// Flash attention, split-bf16 HMMA, double-buffered K/V tiles.
// Block: 256 thr (8 warps x 16 q rows). KT=64.
// Q staged across a FULL stage (hi = tiles 0-1, lo = tiles 2-3).
// =================================================================
#define AT_SSTR  72
#define AT_ROWB  (AT_SSTR * 2)           // 144
#define AT_TILEB (64 * AT_ROWB)          // 9216
#define AT_STAGE (4 * AT_TILEB)          // 36864
#define ATTN_SMEM (2 * AT_STAGE)         // 73728

__device__ __forceinline__ void attn_issue(uint32_t stage_sb, int tid, int head, int k0)
{
#pragma unroll
    for (int i = 0; i < 8; i++) {
        const int e = i * 256 + tid;
        const int arr = e >> 9, idx = e & 511;
        const int row = idx >> 3, c = idx & 7;
        const uint32_t dst = stage_sb + arr * AT_TILEB + row * AT_ROWB + c * 16;
        const __nv_bfloat16* src;
        if (arr == 0)      src = g_Kh  + ((size_t)head * SEQ + k0 + row) * DK + c * 8;
        else if (arr == 1) src = g_Kl  + ((size_t)head * SEQ + k0 + row) * DK + c * 8;
        else if (arr == 2) src = g_Vth + ((size_t)head * DK + row) * SEQ + k0 + c * 8;
        else               src = g_Vtl + ((size_t)head * DK + row) * SEQ + k0 + c * 8;
        cp16(dst, src);
    }
}

__global__ __launch_bounds__(256)
void attn_mma()
{
    extern __shared__ char smem[];
    const uint32_t sb = smem_u32(smem);
    const int tid = threadIdx.x, lane = tid & 31, w = tid >> 5;
    const int head = blockIdx.y;
    const int q0 = (int)(gridDim.x - 1 - blockIdx.x) * 128;
    const int qwb = q0 + w * 16;

    // ---- stage Q across stage0+stage1 area: hi tiles 0-1, lo tiles 2-3 ----
    {
        const __nv_bfloat16* Qh = g_Qh + ((size_t)head * SEQ + q0) * DK;
        const __nv_bfloat16* Ql = g_Ql + ((size_t)head * SEQ + q0) * DK;
#pragma unroll
        for (int i = 0; i < 8; i++) {
            const int e = i * 256 + tid;
            const int half = e >> 10;              // 0 = hi, 1 = lo
            const int idx = e & 1023;
            const int row = idx >> 3, c = idx & 7;
            const uint32_t dst = sb + half * (2 * AT_TILEB) + row * AT_ROWB + c * 16;
            const __nv_bfloat16* src = (half ? Ql : Qh) + (size_t)row * DK + c * 8;
            cp16(dst, src);
        }
        CP_COMMIT(); CP_WAIT(0);
        __syncthreads();
    }
    uint32_t qh[4][4], ql[4][4];
#pragma unroll
    for (int kc = 0; kc < 4; kc++) {
        const uint32_t a = sb + (uint32_t)(w * 16 + (lane & 15)) * AT_ROWB
                         + kc * 32 + ((lane >> 4) << 4);
        ldsm4(qh[kc][0], qh[kc][1], qh[kc][2], qh[kc][3], a);
        ldsm4(ql[kc][0], ql[kc][1], ql[kc][2], ql[kc][3], a + 2 * AT_TILEB);
    }
    __syncthreads();

    float o[8][4];
#pragma unroll
    for (int nt = 0; nt < 8; nt++)
#pragma unroll
        for (int r = 0; r < 4; r++) o[nt][r] = 0.f;
    float mrow0 = -1e30f, mrow1 = -1e30f, lrow0 = 0.f, lrow1 = 0.f;

    const int ktiles = (q0 >> 6) + 2;

    // prologue: tile 0 into stage 0
    attn_issue(sb, tid, head, 0);
    CP_COMMIT();

    for (int t = 0; t < ktiles; t++) {
        const int k0 = t * 64;
        if (t + 1 < ktiles) {
            attn_issue(sb + ((t + 1) & 1) * AT_STAGE, tid, head, k0 + 64);
            CP_COMMIT();
            CP_WAIT(1);
        } else {
            CP_WAIT(0);
        }
        __syncthreads();
        const uint32_t stg = sb + (t & 1) * AT_STAGE;

        // ---- QK^T ----
        float sc[8][4];
#pragma unroll
        for (int nt = 0; nt < 8; nt++)
#pragma unroll
            for (int r = 0; r < 4; r++) sc[nt][r] = 0.f;
#pragma unroll
        for (int kc = 0; kc < 4; kc++)
#pragma unroll
            for (int g = 0; g < 4; g++) {
                uint32_t kh[4], kl[4];
                const uint32_t ad = stg + (uint32_t)(g * 16 + (lane & 7) + ((lane >> 4) << 3)) * AT_ROWB
                                  + kc * 32 + (((lane >> 3) & 1) << 4);
                ldsm4(kh[0], kh[1], kh[2], kh[3], ad);
                ldsm4(kl[0], kl[1], kl[2], kl[3], ad + AT_TILEB);
                mma16816(sc[2 * g],     qh[kc], &kh[0]);
                mma16816(sc[2 * g + 1], qh[kc], &kh[2]);
                mma16816(sc[2 * g],     qh[kc], &kl[0]);
                mma16816(sc[2 * g + 1], qh[kc], &kl[2]);
                mma16816(sc[2 * g],     ql[kc], &kh[0]);
                mma16816(sc[2 * g + 1], ql[kc], &kh[2]);
            }

        // ---- causal mask (diagonal tiles only) ----
        if (k0 + 63 > qwb) {
            const int r0 = qwb + (lane >> 2);
            const int kb = k0 + 2 * (lane & 3);
#pragma unroll
            for (int nt = 0; nt < 8; nt++) {
                const int kk = kb + nt * 8;
                if (kk     > r0)     sc[nt][0] = -1e30f;
                if (kk + 1 > r0)     sc[nt][1] = -1e30f;
                if (kk     > r0 + 8) sc[nt][2] = -1e30f;
                if (kk + 1 > r0 + 8) sc[nt][3] = -1e30f;
            }
        }

        // ---- online softmax (base 2) ----
        float mx0 = sc[0][0], mx1 = sc[0][2];
#pragma unroll
        for (int nt = 0; nt < 8; nt++) {
            mx0 = fmaxf(mx0, fmaxf(sc[nt][0], sc[nt][1]));
            mx1 = fmaxf(mx1, fmaxf(sc[nt][2], sc[nt][3]));
        }
        mx0 = rmax4(mx0); mx1 = rmax4(mx1);
        const float mn0 = fmaxf(mrow0, mx0), mn1 = fmaxf(mrow1, mx1);
        const float c0 = ex2f(mrow0 - mn0), c1 = ex2f(mrow1 - mn1);
        mrow0 = mn0; mrow1 = mn1;
        float s0 = 0.f, s1 = 0.f;
#pragma unroll
        for (int nt = 0; nt < 8; nt++) {
            sc[nt][0] = ex2f(sc[nt][0] - mn0); s0 += sc[nt][0];
            sc[nt][1] = ex2f(sc[nt][1] - mn0); s0 += sc[nt][1];
            sc[nt][2] = ex2f(sc[nt][2] - mn1); s1 += sc[nt][2];
            sc[nt][3] = ex2f(sc[nt][3] - mn1); s1 += sc[nt][3];
        }
        s0 = rsum4(s0); s1 = rsum4(s1);
        lrow0 = lrow0 * c0 + s0;
        lrow1 = lrow1 * c1 + s1;
#pragma unroll
        for (int nt = 0; nt < 8; nt++) {
            o[nt][0] *= c0; o[nt][1] *= c0;
            o[nt][2] *= c1; o[nt][3] *= c1;
        }

        // ---- P @ V ----
#pragma unroll
        for (int kc = 0; kc < 4; kc++) {
            uint32_t ph[4], pl[4];
            split2(sc[2 * kc][0],     sc[2 * kc][1],     ph[0], pl[0]);
            split2(sc[2 * kc][2],     sc[2 * kc][3],     ph[1], pl[1]);
            split2(sc[2 * kc + 1][0], sc[2 * kc + 1][1], ph[2], pl[2]);
            split2(sc[2 * kc + 1][2], sc[2 * kc + 1][3], ph[3], pl[3]);
#pragma unroll
            for (int g = 0; g < 4; g++) {
                uint32_t vh[4], vl[4];
                const uint32_t ad = stg + 2 * AT_TILEB
                    + (uint32_t)(g * 16 + (lane & 7) + ((lane >> 4) << 3)) * AT_ROWB
                    + kc * 32 + (((lane >> 3) & 1) << 4);
                ldsm4(vh[0], vh[1], vh[2], vh[3], ad);
                ldsm4(vl[0], vl[1], vl[2], vl[3], ad + AT_TILEB);
                mma16816(o[2 * g],     ph, &vh[0]);
                mma16816(o[2 * g + 1], ph, &vh[2]);
                mma16816(o[2 * g],     ph, &vl[0]);
                mma16816(o[2 * g + 1], ph, &vl[2]);
                mma16816(o[2 * g],     pl, &vh[0]);
                mma16816(o[2 * g + 1], pl, &vh[2]);
            }
        }
        __syncthreads();
    }

    // ---- epilogue ----
    const float i0 = 1.f / lrow0, i1 = 1.f / lrow1;
    const int r0 = qwb + (lane >> 2);
    const int dbase = 2 * (lane & 3);
#pragma unroll
    for (int nt = 0; nt < 8; nt++) {
        const int d = nt * 8 + dbase;
        uint32_t hi, lo;
        split2(o[nt][0] * i0, o[nt][1] * i0, hi, lo);
        size_t base = ((size_t)head * SEQ + r0) * DK + d;
        *(uint32_t*)&g_Ah[base] = hi;
        *(uint32_t*)&g_Al[base] = lo;
        split2(o[nt][2] * i1, o[nt][3] * i1, hi, lo);
        base = ((size_t)head * SEQ + r0 + 8) * DK + d;
        *(uint32_t*)&g_Ah[base] = hi;
        *(uint32_t*)&g_Al[base] = lo;
    }
}

// =================================================================
extern "C" void kernel_launch(void* const* d_in, const int* in_sizes, int n_in,
                              void* d_out, int out_size)
{
    const float* X  = (const float*)d_in[0];
    const float* Wq = (const float*)d_in[1];
    const float* Wk = (const float*)d_in[2];
    const float* Wv = (const float*)d_in[3];
    const float* Wo = (const float*)d_in[4];
    float* out = (float*)d_out;

    cudaFuncSetAttribute(gemm_qkv_mma, cudaFuncAttributeMaxDynamicSharedMemorySize, GEMM_SMEM);
    cudaFuncSetAttribute(gemm_out_mma, cudaFuncAttributeMaxDynamicSharedMemorySize, GEMM_SMEM);
    cudaFuncSetAttribute(attn_mma,     cudaFuncAttributeMaxDynamicSharedMemorySize, ATTN_SMEM);

    cvt_all<<<8192, 256>>>(X, Wq, Wk, Wv, Wo);

    dim3 gProj(D_MODEL / BN, M_TOTAL / BM, 3);     // (8, 32, 3)
    gemm_qkv_mma<<<gProj, 256, GEMM_SMEM>>>();

    dim3 gAttn(SEQ / 128, HEADS_TOT);              // (16, 32)
    attn_mma<<<gAttn, 256, ATTN_SMEM>>>();

    dim3 gOut(D_MODEL / BN, M_TOTAL / BM);         // (8, 32)
    gemm_out_mma<<<gOut, 256, GEMM_SMEM>>>(out);
}

// round 8
// speedup vs baseline: 4.6323x; 1.0973x over previous
#include <cuda_runtime.h>
#include <cuda_bf16.h>
#include <cstdint>
#include <math.h>

#define D_MODEL   1024
#define NUM_HEADS 16
#define DK        64
#define BATCH     2
#define SEQ       2048
#define M_TOTAL   (BATCH * SEQ)          // 4096
#define HEADS_TOT (BATCH * NUM_HEADS)    // 32

// log2(e)/sqrt(64) folded into Q
#define QSCALE 0.18033688011112042f

// ---------------- scratch (no cudaMalloc allowed) ----------------
__device__ __nv_bfloat16 g_Xh[(size_t)M_TOTAL * D_MODEL];
__device__ __nv_bfloat16 g_Xl[(size_t)M_TOTAL * D_MODEL];
__device__ __nv_bfloat16 g_Wh[4][(size_t)D_MODEL * D_MODEL];
__device__ __nv_bfloat16 g_Wl[4][(size_t)D_MODEL * D_MODEL];
__device__ __nv_bfloat16 g_Qh[(size_t)HEADS_TOT * SEQ * DK];
__device__ __nv_bfloat16 g_Ql[(size_t)HEADS_TOT * SEQ * DK];
__device__ __nv_bfloat16 g_Kh[(size_t)HEADS_TOT * SEQ * DK];
__device__ __nv_bfloat16 g_Kl[(size_t)HEADS_TOT * SEQ * DK];
__device__ __nv_bfloat16 g_Vth[(size_t)HEADS_TOT * DK * SEQ];
__device__ __nv_bfloat16 g_Vtl[(size_t)HEADS_TOT * DK * SEQ];
__device__ __nv_bfloat16 g_Ah[(size_t)HEADS_TOT * SEQ * DK];
__device__ __nv_bfloat16 g_Al[(size_t)HEADS_TOT * SEQ * DK];

// ---------------- ptx helpers ----------------
__device__ __forceinline__ uint32_t smem_u32(const void* p) {
    uint32_t a;
    asm("{ .reg .u64 t; cvta.to.shared.u64 t, %1; cvt.u32.u64 %0, t; }" : "=r"(a) : "l"(p));
    return a;
}
__device__ __forceinline__ void cp16(uint32_t dst, const void* src) {
    asm volatile("cp.async.cg.shared.global [%0], [%1], 16;" :: "r"(dst), "l"(src));
}
#define CP_COMMIT() asm volatile("cp.async.commit_group;" ::: "memory")
#define CP_WAIT(n)  asm volatile("cp.async.wait_group %0;" :: "n"(n) : "memory")

__device__ __forceinline__ void ldsm4(uint32_t& r0, uint32_t& r1, uint32_t& r2, uint32_t& r3,
                                      uint32_t addr) {
    asm volatile("ldmatrix.sync.aligned.m8n8.x4.shared.b16 {%0,%1,%2,%3}, [%4];"
                 : "=r"(r0), "=r"(r1), "=r"(r2), "=r"(r3) : "r"(addr));
}
__device__ __forceinline__ void mma16816(float* d, const uint32_t* a, const uint32_t* b) {
    asm volatile("mma.sync.aligned.m16n8k16.row.col.f32.bf16.bf16.f32 "
        "{%0,%1,%2,%3}, {%4,%5,%6,%7}, {%8,%9}, {%0,%1,%2,%3};"
        : "+f"(d[0]), "+f"(d[1]), "+f"(d[2]), "+f"(d[3])
        : "r"(a[0]), "r"(a[1]), "r"(a[2]), "r"(a[3]), "r"(b[0]), "r"(b[1]));
}
__device__ __forceinline__ void split2(float x, float y, uint32_t& hi, uint32_t& lo) {
    uint32_t h;
    asm("cvt.rn.bf16x2.f32 %0, %1, %2;" : "=r"(h) : "f"(y), "f"(x));
    float hx = __uint_as_float(h << 16);
    float hy = __uint_as_float(h & 0xffff0000u);
    float lx = x - hx, ly = y - hy;
    asm("cvt.rn.bf16x2.f32 %0, %1, %2;" : "=r"(lo) : "f"(ly), "f"(lx));
    hi = h;
}
__device__ __forceinline__ float ex2f(float x) {
    float r; asm("ex2.approx.f32 %0, %1;" : "=f"(r) : "f"(x)); return r;
}
__device__ __forceinline__ float rmax4(float v) {
    v = fmaxf(v, __shfl_xor_sync(0xffffffffu, v, 1));
    v = fmaxf(v, __shfl_xor_sync(0xffffffffu, v, 2));
    return v;
}
__device__ __forceinline__ float rsum4(float v) {
    v += __shfl_xor_sync(0xffffffffu, v, 1);
    v += __shfl_xor_sync(0xffffffffu, v, 2);
    return v;
}

// =================================================================
// fused fp32 -> (hi, lo) bf16 split for X + 4 weights (one launch)
// =================================================================
__global__ __launch_bounds__(256)
void cvt_all(const float* __restrict__ X,  const float* __restrict__ Wq,
             const float* __restrict__ Wk, const float* __restrict__ Wv,
             const float* __restrict__ Wo)
{
    const int bid = blockIdx.x;
    const float* src;
    __nv_bfloat16 *hi, *lo;
    int i;
    if (bid < 4096) {
        src = X; hi = g_Xh; lo = g_Xl;
        i = bid * 256 + threadIdx.x;
    } else {
        const int seg = (bid - 4096) >> 10;
        i = ((bid - 4096) & 1023) * 256 + threadIdx.x;
        src = seg == 0 ? Wq : seg == 1 ? Wk : seg == 2 ? Wv : Wo;
        hi = g_Wh[seg]; lo = g_Wl[seg];
    }
    float4 v = ((const float4*)src)[i];
    uint32_t h0, l0, h1, l1;
    split2(v.x, v.y, h0, l0);
    split2(v.z, v.w, h1, l1);
    ((uint2*)hi)[i] = make_uint2(h0, h1);
    ((uint2*)lo)[i] = make_uint2(l0, l1);
}

// =================================================================
// split-bf16 HMMA GEMM: block 128x128, BK=32, 8 warps (4x2), warp 32x64.
// MMAs issued TERM-MAJOR: 16x hh, 16x hl, 16x lh (same-acc distance 16).
// =================================================================
#define BM 128
#define BN 128
#define BK 32
#define SSTR   40
#define TILE_B (BM * SSTR * 2)
#define STAGE_B (4 * TILE_B)
#define GEMM_SMEM (2 * STAGE_B)          // 81920 B

template<bool QKV>
__device__ __forceinline__ void issue_copies(uint32_t stage_sb, int tid, int m0, int n0, int kc,
                                             const __nv_bfloat16* __restrict__ Wh,
                                             const __nv_bfloat16* __restrict__ Wl)
{
    const int k0 = kc * BK;
#pragma unroll
    for (int o = 0; o < 8; o++) {
        const int e    = o * 256 + tid;
        const int tile = e >> 9;
        const int idx  = e & 511;
        const int r = idx >> 2, c = idx & 3;
        const uint32_t dst = stage_sb + tile * TILE_B + r * (SSTR * 2) + c * 16;
        const __nv_bfloat16* src;
        if (tile < 2) {
            size_t ai;
            if (QKV) {
                ai = (size_t)(m0 + r) * D_MODEL + k0 + c * 8;
            } else {
                const int m = m0 + r;
                ai = (((size_t)(m >> 11) * NUM_HEADS + (k0 >> 6)) * SEQ + (m & (SEQ - 1))) * DK
                     + (k0 & 63) + c * 8;
            }
            src = (tile == 0 ? (QKV ? g_Xh : g_Ah) : (QKV ? g_Xl : g_Al)) + ai;
        } else {
            const size_t bi = (size_t)(n0 + r) * D_MODEL + k0 + c * 8;
            src = (tile == 2 ? Wh : Wl) + bi;
        }
        cp16(dst, src);
    }
}

__device__ __forceinline__ void mma_stage(uint32_t Abase, int lane, int wm, int wn,
                                          float acc[2][8][4])
{
#pragma unroll
    for (int h = 0; h < 2; h++) {
        uint32_t ah[2][4], al[2][4];
#pragma unroll
        for (int mt = 0; mt < 2; mt++) {
            const uint32_t addr = Abase
                + (uint32_t)(wm * 32 + mt * 16 + (lane & 15)) * (SSTR * 2)
                + h * 32 + ((lane >> 4) << 4);
            ldsm4(ah[mt][0], ah[mt][1], ah[mt][2], ah[mt][3], addr);
            ldsm4(al[mt][0], al[mt][1], al[mt][2], al[mt][3], addr + TILE_B);
        }
        uint32_t bh[4][4], bl[4][4];
#pragma unroll
        for (int nt = 0; nt < 4; nt++) {
            const uint32_t addr = Abase + 2 * TILE_B
                + (uint32_t)(wn * 64 + nt * 16 + (lane & 7) + ((lane >> 4) << 3)) * (SSTR * 2)
                + h * 32 + (((lane >> 3) & 1) << 4);
            ldsm4(bh[nt][0], bh[nt][1], bh[nt][2], bh[nt][3], addr);
            ldsm4(bl[nt][0], bl[nt][1], bl[nt][2], bl[nt][3], addr + TILE_B);
        }
        // term-major: all hh, then all hl, then all lh
#pragma unroll
        for (int mt = 0; mt < 2; mt++)
#pragma unroll
            for (int nt = 0; nt < 4; nt++) {
                mma16816(acc[mt][2 * nt],     ah[mt], &bh[nt][0]);
                mma16816(acc[mt][2 * nt + 1], ah[mt], &bh[nt][2]);
            }
#pragma unroll
        for (int mt = 0; mt < 2; mt++)
#pragma unroll
            for (int nt = 0; nt < 4; nt++) {
                mma16816(acc[mt][2 * nt],     ah[mt], &bl[nt][0]);
                mma16816(acc[mt][2 * nt + 1], ah[mt], &bl[nt][2]);
            }
#pragma unroll
        for (int mt = 0; mt < 2; mt++)
#pragma unroll
            for (int nt = 0; nt < 4; nt++) {
                mma16816(acc[mt][2 * nt],     al[mt], &bh[nt][0]);
                mma16816(acc[mt][2 * nt + 1], al[mt], &bh[nt][2]);
            }
    }
}

template<bool QKV>
__device__ __forceinline__ void gemm_body(float acc[2][8][4], uint32_t sb, int tid,
                                          int m0, int n0,
                                          const __nv_bfloat16* __restrict__ Wh,
                                          const __nv_bfloat16* __restrict__ Wl)
{
    const int lane = tid & 31, wid = tid >> 5;
    const int wm = wid >> 1, wn = wid & 1;
    const int NKC = D_MODEL / BK;

    issue_copies<QKV>(sb, tid, m0, n0, 0, Wh, Wl);
    CP_COMMIT();
    for (int kc = 0; kc < NKC; kc++) {
        if (kc + 1 < NKC) {
            issue_copies<QKV>(sb + ((kc + 1) & 1) * STAGE_B, tid, m0, n0, kc + 1, Wh, Wl);
            CP_COMMIT();
            CP_WAIT(1);
        } else {
            CP_WAIT(0);
        }
        __syncthreads();
        mma_stage(sb + (kc & 1) * STAGE_B, lane, wm, wn, acc);
        __syncthreads();
    }
}

__global__ __launch_bounds__(256, 2)
void gemm_qkv_mma()
{
    extern __shared__ char smem[];
    const uint32_t sb = smem_u32(smem);
    const int tid = threadIdx.x;
    const int z  = blockIdx.z;
    const int m0 = blockIdx.y * BM, n0 = blockIdx.x * BN;

    float acc[2][8][4];
#pragma unroll
    for (int a = 0; a < 2; a++)
#pragma unroll
        for (int b = 0; b < 8; b++)
#pragma unroll
            for (int c = 0; c < 4; c++) acc[a][b][c] = 0.f;

    gemm_body<true>(acc, sb, tid, m0, n0, g_Wh[z], g_Wl[z]);

    const float scale = (z == 0) ? QSCALE : 1.0f;
    const int lane = tid & 31, wid = tid >> 5;
    const int wm = wid >> 1, wn = wid & 1;
    const int h = ((n0 + wn * 64) >> 6);
#pragma unroll
    for (int mt = 0; mt < 2; mt++)
#pragma unroll
        for (int rr = 0; rr < 2; rr++) {
            const int m = m0 + wm * 32 + mt * 16 + rr * 8 + (lane >> 2);
            const int b = m >> 11, s = m & (SEQ - 1);
            const int head = b * NUM_HEADS + h;
#pragma unroll
            for (int j = 0; j < 8; j++) {
                const int t = j * 8 + 2 * (lane & 3);
                const float x = acc[mt][j][2 * rr] * scale;
                const float y = acc[mt][j][2 * rr + 1] * scale;
                if (z == 2) {
                    const size_t base = ((size_t)head * DK + t) * SEQ + s;
                    __nv_bfloat16 hx = __float2bfloat16(x);
                    __nv_bfloat16 hy = __float2bfloat16(y);
                    g_Vth[base]       = hx;
                    g_Vtl[base]       = __float2bfloat16(x - __bfloat162float(hx));
                    g_Vth[base + SEQ] = hy;
                    g_Vtl[base + SEQ] = __float2bfloat16(y - __bfloat162float(hy));
                } else {
                    uint32_t hi, lo;
                    split2(x, y, hi, lo);
                    const size_t base = ((size_t)head * SEQ + s) * DK + t;
                    if (z == 0) {
                        *(uint32_t*)&g_Qh[base] = hi;
                        *(uint32_t*)&g_Ql[base] = lo;
                    } else {
                        *(uint32_t*)&g_Kh[base] = hi;
                        *(uint32_t*)&g_Kl[base] = lo;
                    }
                }
            }
        }
}

__global__ __launch_bounds__(256, 2)
void gemm_out_mma(float* __restrict__ C)
{
    extern __shared__ char smem[];
    const uint32_t sb = smem_u32(smem);
    const int tid = threadIdx.x;
    const int m0 = blockIdx.y * BM, n0 = blockIdx.x * BN;

    float acc[2][8][4];
#pragma unroll
    for (int a = 0; a < 2; a++)
#pragma unroll
        for (int b = 0; b < 8; b++)
#pragma unroll
            for (int c = 0; c < 4; c++) acc[a][b][c] = 0.f;

    gemm_body<false>(acc, sb, tid, m0, n0, g_Wh[3], g_Wl[3]);

    const int lane = tid & 31, wid = tid >> 5;
    const int wm = wid >> 1, wn = wid & 1;
#pragma unroll
    for (int mt = 0; mt < 2; mt++)
#pragma unroll
        for (int rr = 0; rr < 2; rr++) {
            const int m = m0 + wm * 32 + mt * 16 + rr * 8 + (lane >> 2);
            float* dst = &C[(size_t)m * D_MODEL + n0 + wn * 64];
#pragma unroll
            for (int j = 0; j < 8; j++) {
                const int t = j * 8 + 2 * (lane & 3);
                float2 v = rr == 0 ? make_float2(acc[mt][j][0], acc[mt][j][1])
                                   : make_float2(acc[mt][j][2], acc[mt][j][3]);
                *(float2*)&dst[t] = v;
            }
        }
}

// =================================================================
// Flash attention, split-bf16 HMMA, double-buffered K/V tiles.
// QK/PV restructured: g-pairs, term-major MMA issue (same-acc dist 4).
// =================================================================
#define AT_SSTR  72
#define AT_ROWB  (AT_SSTR * 2)           // 144
#define AT_TILEB (64 * AT_ROWB)          // 9216
#define AT_STAGE (4 * AT_TILEB)          // 36864
#define ATTN_SMEM (2 * AT_STAGE)         // 73728

__device__ __forceinline__ void attn_issue(uint32_t stage_sb, int tid, int head, int k0)
{
#pragma unroll
    for (int i = 0; i < 8; i++) {
        const int e = i * 256 + tid;
        const int arr = e >> 9, idx = e & 511;
        const int row = idx >> 3, c = idx & 7;
        const uint32_t dst = stage_sb + arr * AT_TILEB + row * AT_ROWB + c * 16;
        const __nv_bfloat16* src;
        if (arr == 0)      src = g_Kh  + ((size_t)head * SEQ + k0 + row) * DK + c * 8;
        else if (arr == 1) src = g_Kl  + ((size_t)head * SEQ + k0 + row) * DK + c * 8;
        else if (arr == 2) src = g_Vth + ((size_t)head * DK + row) * SEQ + k0 + c * 8;
        else               src = g_Vtl + ((size_t)head * DK + row) * SEQ + k0 + c * 8;
        cp16(dst, src);
    }
}

__global__ __launch_bounds__(256)
void attn_mma()
{
    extern __shared__ char smem[];
    const uint32_t sb = smem_u32(smem);
    const int tid = threadIdx.x, lane = tid & 31, w = tid >> 5;
    const int head = blockIdx.y;
    const int q0 = (int)(gridDim.x - 1 - blockIdx.x) * 128;
    const int qwb = q0 + w * 16;

    // ---- stage Q across stage0+stage1 area: hi tiles 0-1, lo tiles 2-3 ----
    {
        const __nv_bfloat16* Qh = g_Qh + ((size_t)head * SEQ + q0) * DK;
        const __nv_bfloat16* Ql = g_Ql + ((size_t)head * SEQ + q0) * DK;
#pragma unroll
        for (int i = 0; i < 8; i++) {
            const int e = i * 256 + tid;
            const int half = e >> 10;              // 0 = hi, 1 = lo
            const int idx = e & 1023;
            const int row = idx >> 3, c = idx & 7;
            const uint32_t dst = sb + half * (2 * AT_TILEB) + row * AT_ROWB + c * 16;
            const __nv_bfloat16* src = (half ? Ql : Qh) + (size_t)row * DK + c * 8;
            cp16(dst, src);
        }
        CP_COMMIT(); CP_WAIT(0);
        __syncthreads();
    }
    uint32_t qh[4][4], ql[4][4];
#pragma unroll
    for (int kc = 0; kc < 4; kc++) {
        const uint32_t a = sb + (uint32_t)(w * 16 + (lane & 15)) * AT_ROWB
                         + kc * 32 + ((lane >> 4) << 4);
        ldsm4(qh[kc][0], qh[kc][1], qh[kc][2], qh[kc][3], a);
        ldsm4(ql[kc][0], ql[kc][1], ql[kc][2], ql[kc][3], a + 2 * AT_TILEB);
    }
    __syncthreads();

    float o[8][4];
#pragma unroll
    for (int nt = 0; nt < 8; nt++)
#pragma unroll
        for (int r = 0; r < 4; r++) o[nt][r] = 0.f;
    float mrow0 = -1e30f, mrow1 = -1e30f, lrow0 = 0.f, lrow1 = 0.f;

    const int ktiles = (q0 >> 6) + 2;

    attn_issue(sb, tid, head, 0);
    CP_COMMIT();

    for (int t = 0; t < ktiles; t++) {
        const int k0 = t * 64;
        if (t + 1 < ktiles) {
            attn_issue(sb + ((t + 1) & 1) * AT_STAGE, tid, head, k0 + 64);
            CP_COMMIT();
            CP_WAIT(1);
        } else {
            CP_WAIT(0);
        }
        __syncthreads();
        const uint32_t stg = sb + (t & 1) * AT_STAGE;

        // ---- QK^T (g-pairs, term-major) ----
        float sc[8][4];
#pragma unroll
        for (int nt = 0; nt < 8; nt++)
#pragma unroll
            for (int r = 0; r < 4; r++) sc[nt][r] = 0.f;
#pragma unroll
        for (int kc = 0; kc < 4; kc++)
#pragma unroll
            for (int gp = 0; gp < 2; gp++) {
                uint32_t kh[2][4], kl[2][4];
#pragma unroll
                for (int gi = 0; gi < 2; gi++) {
                    const int g = gp * 2 + gi;
                    const uint32_t ad = stg
                        + (uint32_t)(g * 16 + (lane & 7) + ((lane >> 4) << 3)) * AT_ROWB
                        + kc * 32 + (((lane >> 3) & 1) << 4);
                    ldsm4(kh[gi][0], kh[gi][1], kh[gi][2], kh[gi][3], ad);
                    ldsm4(kl[gi][0], kl[gi][1], kl[gi][2], kl[gi][3], ad + AT_TILEB);
                }
#pragma unroll
                for (int gi = 0; gi < 2; gi++) {
                    const int g = gp * 2 + gi;
                    mma16816(sc[2 * g],     qh[kc], &kh[gi][0]);
                    mma16816(sc[2 * g + 1], qh[kc], &kh[gi][2]);
                }
#pragma unroll
                for (int gi = 0; gi < 2; gi++) {
                    const int g = gp * 2 + gi;
                    mma16816(sc[2 * g],     qh[kc], &kl[gi][0]);
                    mma16816(sc[2 * g + 1], qh[kc], &kl[gi][2]);
                }
#pragma unroll
                for (int gi = 0; gi < 2; gi++) {
                    const int g = gp * 2 + gi;
                    mma16816(sc[2 * g],     ql[kc], &kh[gi][0]);
                    mma16816(sc[2 * g + 1], ql[kc], &kh[gi][2]);
                }
            }

        // ---- causal mask (diagonal tiles only) ----
        if (k0 + 63 > qwb) {
            const int r0 = qwb + (lane >> 2);
            const int kb = k0 + 2 * (lane & 3);
#pragma unroll
            for (int nt = 0; nt < 8; nt++) {
                const int kk = kb + nt * 8;
                if (kk     > r0)     sc[nt][0] = -1e30f;
                if (kk + 1 > r0)     sc[nt][1] = -1e30f;
                if (kk     > r0 + 8) sc[nt][2] = -1e30f;
                if (kk + 1 > r0 + 8) sc[nt][3] = -1e30f;
            }
        }

        // ---- online softmax (base 2) ----
        float mx0 = sc[0][0], mx1 = sc[0][2];
#pragma unroll
        for (int nt = 0; nt < 8; nt++) {
            mx0 = fmaxf(mx0, fmaxf(sc[nt][0], sc[nt][1]));
            mx1 = fmaxf(mx1, fmaxf(sc[nt][2], sc[nt][3]));
        }
        mx0 = rmax4(mx0); mx1 = rmax4(mx1);
        const float mn0 = fmaxf(mrow0, mx0), mn1 = fmaxf(mrow1, mx1);
        const float c0 = ex2f(mrow0 - mn0), c1 = ex2f(mrow1 - mn1);
        mrow0 = mn0; mrow1 = mn1;
        float s0 = 0.f, s1 = 0.f;
#pragma unroll
        for (int nt = 0; nt < 8; nt++) {
            sc[nt][0] = ex2f(sc[nt][0] - mn0); s0 += sc[nt][0];
            sc[nt][1] = ex2f(sc[nt][1] - mn0); s0 += sc[nt][1];
            sc[nt][2] = ex2f(sc[nt][2] - mn1); s1 += sc[nt][2];
            sc[nt][3] = ex2f(sc[nt][3] - mn1); s1 += sc[nt][3];
        }
        s0 = rsum4(s0); s1 = rsum4(s1);
        lrow0 = lrow0 * c0 + s0;
        lrow1 = lrow1 * c1 + s1;
#pragma unroll
        for (int nt = 0; nt < 8; nt++) {
            o[nt][0] *= c0; o[nt][1] *= c0;
            o[nt][2] *= c1; o[nt][3] *= c1;
        }

        // ---- P @ V (g-pairs, term-major) ----
#pragma unroll
        for (int kc = 0; kc < 4; kc++) {
            uint32_t ph[4], pl[4];
            split2(sc[2 * kc][0],     sc[2 * kc][1],     ph[0], pl[0]);
            split2(sc[2 * kc][2],     sc[2 * kc][3],     ph[1], pl[1]);
            split2(sc[2 * kc + 1][0], sc[2 * kc + 1][1], ph[2], pl[2]);
            split2(sc[2 * kc + 1][2], sc[2 * kc + 1][3], ph[3], pl[3]);
#pragma unroll
            for (int gp = 0; gp < 2; gp++) {
                uint32_t vh[2][4], vl[2][4];
#pragma unroll
                for (int gi = 0; gi < 2; gi++) {
                    const int g = gp * 2 + gi;
                    const uint32_t ad = stg + 2 * AT_TILEB
                        + (uint32_t)(g * 16 + (lane & 7) + ((lane >> 4) << 3)) * AT_ROWB
                        + kc * 32 + (((lane >> 3) & 1) << 4);
                    ldsm4(vh[gi][0], vh[gi][1], vh[gi][2], vh[gi][3], ad);
                    ldsm4(vl[gi][0], vl[gi][1], vl[gi][2], vl[gi][3], ad + AT_TILEB);
                }
#pragma unroll
                for (int gi = 0; gi < 2; gi++) {
                    const int g = gp * 2 + gi;
                    mma16816(o[2 * g],     ph, &vh[gi][0]);
                    mma16816(o[2 * g + 1], ph, &vh[gi][2]);
                }
#pragma unroll
                for (int gi = 0; gi < 2; gi++) {
                    const int g = gp * 2 + gi;
                    mma16816(o[2 * g],     ph, &vl[gi][0]);
                    mma16816(o[2 * g + 1], ph, &vl[gi][2]);
                }
#pragma unroll
                for (int gi = 0; gi < 2; gi++) {
                    const int g = gp * 2 + gi;
                    mma16816(o[2 * g],     pl, &vh[gi][0]);
                    mma16816(o[2 * g + 1], pl, &vh[gi][2]);
                }
            }
        }
        __syncthreads();
    }

    // ---- epilogue ----
    const float i0 = 1.f / lrow0, i1 = 1.f / lrow1;
    const int r0 = qwb + (lane >> 2);
    const int dbase = 2 * (lane & 3);
#pragma unroll
    for (int nt = 0; nt < 8; nt++) {
        const int d = nt * 8 + dbase;
        uint32_t hi, lo;
        split2(o[nt][0] * i0, o[nt][1] * i0, hi, lo);
        size_t base = ((size_t)head * SEQ + r0) * DK + d;
        *(uint32_t*)&g_Ah[base] = hi;
        *(uint32_t*)&g_Al[base] = lo;
        split2(o[nt][2] * i1, o[nt][3] * i1, hi, lo);
        base = ((size_t)head * SEQ + r0 + 8) * DK + d;
        *(uint32_t*)&g_Ah[base] = hi;
        *(uint32_t*)&g_Al[base] = lo;
    }
}

// =================================================================
extern "C" void kernel_launch(void* const* d_in, const int* in_sizes, int n_in,
                              void* d_out, int out_size)
{
    const float* X  = (const float*)d_in[0];
    const float* Wq = (const float*)d_in[1];
    const float* Wk = (const float*)d_in[2];
    const float* Wv = (const float*)d_in[3];
    const float* Wo = (const float*)d_in[4];
    float* out = (float*)d_out;

    cudaFuncSetAttribute(gemm_qkv_mma, cudaFuncAttributeMaxDynamicSharedMemorySize, GEMM_SMEM);
    cudaFuncSetAttribute(gemm_out_mma, cudaFuncAttributeMaxDynamicSharedMemorySize, GEMM_SMEM);
    cudaFuncSetAttribute(attn_mma,     cudaFuncAttributeMaxDynamicSharedMemorySize, ATTN_SMEM);

    cvt_all<<<8192, 256>>>(X, Wq, Wk, Wv, Wo);

    dim3 gProj(D_MODEL / BN, M_TOTAL / BM, 3);     // (8, 32, 3)
    gemm_qkv_mma<<<gProj, 256, GEMM_SMEM>>>();

    dim3 gAttn(SEQ / 128, HEADS_TOT);              // (16, 32)
    attn_mma<<<gAttn, 256, ATTN_SMEM>>>();

    dim3 gOut(D_MODEL / BN, M_TOTAL / BM);         // (8, 32)
    gemm_out_mma<<<gOut, 256, GEMM_SMEM>>>(out);
}